// round 14
// baseline (speedup 1.0000x reference)
#include <cuda_runtime.h>
#include <math.h>

// Problem constants
#define Bn 4
#define Nn 4096
#define Kn 16
#define DP 64
#define DM 128
#define NODES (Bn*Nn)            // 16384
#define ATT_OFF (NODES*DP)       // out region first, attn after
#define SCALE_F 0.08838834764831845f
#define FINF __int_as_float(0x7F800000)
#define KEY_INF 0xFFFFFFFFFFFFFFFFULL
#define HS 132                   // padded sH row stride (floats)

typedef unsigned long long ull;

// Scratch (device globals -- no allocation allowed)
__device__ int    g_idx[NODES*Kn];
__device__ float  g_q [NODES*DM];
__device__ float  g_k [NODES*DM];
__device__ float  g_v [NODES*DM];
__device__ float  g_posbuf[(size_t)NODES*Kn*DM];   // 128 MiB static scratch
__device__ float4 g_sp[NODES];                     // x-sorted (x,y,z,idx_bits)
// Pre-split tf32 weight fragments: [weight][quarter][n*16 + kt*4 + tig]
// uint4 = (b0_hi, b1_hi, b0_lo, b1_lo), b0: k=kt*8+tig, b1: k+4.
__device__ uint4  g_wfrag[3][4][2048];

// ---------------------------------------------------------------------------
// helpers
// ---------------------------------------------------------------------------
__device__ __forceinline__ ull pk2(float lo, float hi) {
    ull r;
    asm("mov.b64 %0, {%1,%2};" : "=l"(r)
        : "r"(__float_as_uint(lo)), "r"(__float_as_uint(hi)));
    return r;
}
__device__ __forceinline__ ull dup2f(float v) {
    ull r; unsigned u = __float_as_uint(v);
    asm("mov.b64 %0, {%1,%1};" : "=l"(r) : "r"(u));
    return r;
}
__device__ __forceinline__ void fma2(ull& d, ull a, ull b) {
    asm("fma.rn.f32x2 %0, %1, %2, %0;" : "+l"(d) : "l"(a), "l"(b));
}
__device__ __forceinline__ float2 up2(ull v) {
    unsigned lo, hi;
    asm("mov.b64 {%0,%1}, %2;" : "=r"(lo), "=r"(hi) : "l"(v));
    return make_float2(__uint_as_float(lo), __uint_as_float(hi));
}
__device__ __forceinline__ unsigned tf32cvt(float x) {
    unsigned r;
    asm("cvt.rna.tf32.f32 %0, %1;" : "=r"(r) : "f"(x));
    return r;
}
#define MMA8(c, a0,a1,a2,a3, b0,b1) \
    asm volatile("mma.sync.aligned.m16n8k8.row.col.f32.tf32.tf32.f32 " \
        "{%0,%1,%2,%3}, {%4,%5,%6,%7}, {%8,%9}, {%0,%1,%2,%3};" \
        : "+f"(c[0]), "+f"(c[1]), "+f"(c[2]), "+f"(c[3]) \
        : "r"(a0), "r"(a1), "r"(a2), "r"(a3), "r"(b0), "r"(b1))

// ---------------------------------------------------------------------------
// Kernel 0a: per-batch bitonic sort of points by x. grid Bn x 1024 threads.
// ---------------------------------------------------------------------------
__global__ void __launch_bounds__(1024) sort_kernel(const float* __restrict__ xyz) {
    __shared__ float skey[Nn];
    __shared__ int   sval[Nn];
    int t = threadIdx.x;
    int b = blockIdx.x;
    const float* base = xyz + (size_t)b * Nn * 3;
    for (int i = t; i < Nn; i += 1024) { skey[i] = base[i*3]; sval[i] = i; }
    __syncthreads();
    for (int k = 2; k <= Nn; k <<= 1) {
        for (int j = k >> 1; j > 0; j >>= 1) {
            for (int e = t; e < Nn; e += 1024) {
                int p = e ^ j;
                if (p > e) {
                    bool up = ((e & k) == 0);
                    float a = skey[e], c = skey[p];
                    if ((a > c) == up) {
                        skey[e] = c; skey[p] = a;
                        int tv = sval[e]; sval[e] = sval[p]; sval[p] = tv;
                    }
                }
            }
            __syncthreads();
        }
    }
    for (int i = t; i < Nn; i += 1024) {
        int id = sval[i];
        g_sp[b*Nn + i] = make_float4(skey[i], base[id*3 + 1], base[id*3 + 2],
                                     __int_as_float(id));
    }
}

// ---------------------------------------------------------------------------
// Kernel 0b: pre-split d2/g1/g2 into tf32 hi/lo fragment-ordered uint4.
// 24576 threads, one frag each.
// ---------------------------------------------------------------------------
__global__ void __launch_bounds__(256) wsplit_kernel(
    const float* __restrict__ d2, const float* __restrict__ g1,
    const float* __restrict__ g2)
{
    int gid = blockIdx.x * 256 + threadIdx.x;   // 0..24575
    int w  = gid >> 13;            // weight id (8192 frags each)
    int f  = gid & 8191;
    int q  = f >> 11;              // quarter
    int r  = f & 2047;
    int n  = r >> 4;
    int ff = r & 15;
    int kt = ff >> 2, tig = ff & 3;
    const float* W = (w == 0) ? d2 : (w == 1) ? g1 : g2;
    int k0 = q*32 + kt*8 + tig;
    float x0 = W[(size_t)k0 * 128 + n];
    float x1 = W[(size_t)(k0 + 4) * 128 + n];
    unsigned h0 = tf32cvt(x0), h1 = tf32cvt(x1);
    unsigned l0 = tf32cvt(x0 - __uint_as_float(h0));
    unsigned l1 = tf32cvt(x1 - __uint_as_float(h1));
    g_wfrag[w][q][r] = make_uint4(h0, h1, l0, l1);
}

// ---------------------------------------------------------------------------
// Kernel 1: warp-per-query windowed KNN on x-sorted points (R9, proven).
// ---------------------------------------------------------------------------
__global__ void __launch_bounds__(512) knn_kernel() {
    extern __shared__ float4 spts[];       // 4096 * 16B = 65536
    int t = threadIdx.x;
    int b = blockIdx.y;
    for (int i = t; i < Nn; i += 512) spts[i] = g_sp[b*Nn + i];
    __syncthreads();

    const unsigned full = 0xffffffffu;
    int lane = t & 31;
    int r = blockIdx.x * 16 + (t >> 5);

    float4 me = spts[r];
    float qx = me.x, qy = me.y, qz = me.z;
    int qid = __float_as_int(me.w);

    ull key = KEY_INF;
    if (lane == 0) key = (unsigned)qid;
    ull wk = __shfl_sync(full, key, 15);

    bool isL = lane < 16;
    int lo = r - 1, hi = r + 1;
    bool aliveL = true, aliveR = true;

    while (aliveL || aliveR) {
        ull  ckey = KEY_INF;
        float dxx = FINF;
        bool inr = false;
        int cand = isL ? (lo - lane) : (hi + (lane - 16));
        if (isL) inr = aliveL && (cand >= 0);
        else     inr = aliveR && (cand < Nn);
        if (inr) {
            float4 p = spts[cand];
            float dx = qx - p.x, dy = qy - p.y, dz = qz - p.z;
            dxx = __fmul_rn(dx, dx);
            float d = __fadd_rn(__fadd_rn(dxx, __fmul_rn(dy,dy)),
                                __fmul_rn(dz,dz));
            ckey = ((ull)__float_as_uint(d) << 32) |
                   (unsigned)__float_as_int(p.w);
        }

        unsigned ball = __ballot_sync(full, inr && ckey < wk);
        while (ball) {
            int s = __ffs(ball) - 1; ball &= ball - 1;
            ull k = __shfl_sync(full, ckey, s);
            if (k >= wk) continue;
            unsigned bl = __ballot_sync(full, isL && key < k);
            int pos = __popc(bl);
            ull up = __shfl_up_sync(full, key, 1);
            if (isL) {
                if (lane == pos) key = k;
                else if (lane > pos) key = up;
            }
            wk = __shfl_sync(full, key, 15);
        }

        float worstd = __uint_as_float((unsigned)(wk >> 32));
        float dxx15 = __shfl_sync(full, dxx, 15);
        float dxx31 = __shfl_sync(full, dxx, 31);
        int   inr15 = __shfl_sync(full, (int)inr, 15);
        int   inr31 = __shfl_sync(full, (int)inr, 31);
        aliveL = aliveL && inr15 && !(dxx15 > worstd);
        aliveR = aliveR && inr31 && !(dxx31 > worstd);
        lo -= 16; hi += 16;
    }

    if (isL)
        g_idx[((size_t)b*Nn + qid) * Kn + lane] =
            (int)(unsigned)(key & 0xffffffffu);
}

// ---------------------------------------------------------------------------
// proj kernel GEMM (scalar f32x2, proven) helpers
// ---------------------------------------------------------------------------
template<int KD, int AS>
__device__ __forceinline__ void gemm_r8(ull acc[8][4],
                                        const float* __restrict__ sA,
                                        const float* __restrict__ sW, int t) {
    const int c0 = (t & 15) * 8;
    const int r0 = (t >> 4) * 8;
#pragma unroll 2
    for (int kk = 0; kk < KD; kk += 4) {
        float4 a4[8];
#pragma unroll
        for (int i = 0; i < 8; i++)
            a4[i] = *(const float4*)(sA + (r0 + i) * AS + kk);
#pragma unroll
        for (int kq = 0; kq < 4; kq++) {
            const float* wr = sW + (kk + kq) * 128 + c0;
            ulonglong2 wl = *(const ulonglong2*)(wr);
            ulonglong2 wh = *(const ulonglong2*)(wr + 4);
#pragma unroll
            for (int i = 0; i < 8; i++) {
                float av = (kq == 0) ? a4[i].x : (kq == 1) ? a4[i].y
                         : (kq == 2) ? a4[i].z : a4[i].w;
                ull ad = dup2f(av);
                fma2(acc[i][0], ad, wl.x);
                fma2(acc[i][1], ad, wl.y);
                fma2(acc[i][2], ad, wh.x);
                fma2(acc[i][3], ad, wh.y);
            }
        }
    }
}
__device__ __forceinline__ void init_r8(ull acc[8][4], const float* __restrict__ bias, int t) {
    const int c0 = (t & 15) * 8;
#pragma unroll
    for (int j = 0; j < 4; j++) {
        ull b2 = pk2(bias[c0 + 2*j], bias[c0 + 2*j + 1]);
#pragma unroll
        for (int i = 0; i < 8; i++) acc[i][j] = b2;
    }
}
template<bool RELU>
__device__ __forceinline__ void store_r8(float* __restrict__ dst, int stride,
                                         ull acc[8][4], int t) {
    const int c0 = (t & 15) * 8;
    const int r0 = (t >> 4) * 8;
#pragma unroll
    for (int i = 0; i < 8; i++) {
        float2 p0 = up2(acc[i][0]), p1 = up2(acc[i][1]);
        float2 p2 = up2(acc[i][2]), p3 = up2(acc[i][3]);
        float4 lo = make_float4(p0.x, p0.y, p1.x, p1.y);
        float4 hi = make_float4(p2.x, p2.y, p3.x, p3.y);
        if (RELU) {
            lo.x = fmaxf(lo.x, 0.f); lo.y = fmaxf(lo.y, 0.f);
            lo.z = fmaxf(lo.z, 0.f); lo.w = fmaxf(lo.w, 0.f);
            hi.x = fmaxf(hi.x, 0.f); hi.y = fmaxf(hi.y, 0.f);
            hi.z = fmaxf(hi.z, 0.f); hi.w = fmaxf(hi.w, 0.f);
        }
        *(float4*)(dst + (size_t)(r0 + i) * stride + c0)     = lo;
        *(float4*)(dst + (size_t)(r0 + i) * stride + c0 + 4) = hi;
    }
}
__device__ __forceinline__ void copyW(float* __restrict__ dst,
                                      const float* __restrict__ src, int n4, int t) {
    for (int o = t; o < n4; o += 256)
        *(float4*)(dst + o*4) = *(const float4*)(src + o*4);
}

// ---------------------------------------------------------------------------
// Kernel 2: fused projections. 128 rows/CTA, 256 threads, grid 128.
// ---------------------------------------------------------------------------
__global__ void __launch_bounds__(256, 2) proj_kernel(
    const float* __restrict__ feats,
    const float* __restrict__ fc1_w, const float* __restrict__ fc1_b,
    const float* __restrict__ wq, const float* __restrict__ wk,
    const float* __restrict__ wv)
{
    extern __shared__ float sm2[];
    float* sW = sm2;            // 8192 floats (32KB)
    float* sX = sm2 + 8192;     // 16384 floats (64KB)
    int t = threadIdx.x;
    int g0 = blockIdx.x * 128;

    copyW(sX, feats + (size_t)g0*64, 2048, t);
    copyW(sW, fc1_w, 2048, t);
    __syncthreads();

    ull acc[8][4];
    init_r8(acc, fc1_b, t);
    gemm_r8<64, 64>(acc, sX, sW, t);
    __syncthreads();
    store_r8<false>(sX, 128, acc, t);
    copyW(sW, wq, 2048, t);
    __syncthreads();

    const float* ws[3] = {wq, wk, wv};
    float* outs[3] = {g_q, g_k, g_v};
#pragma unroll
    for (int m = 0; m < 3; m++) {
#pragma unroll
        for (int j = 0; j < 4; j++)
#pragma unroll
            for (int i = 0; i < 8; i++) acc[i][j] = 0ULL;
        gemm_r8<64, 128>(acc, sX, sW, t);
        __syncthreads();
        copyW(sW, ws[m] + 8192, 2048, t);
        __syncthreads();
        gemm_r8<64, 128>(acc, sX + 64, sW, t);
        store_r8<false>(outs[m] + (size_t)g0*128, 128, acc, t);
        if (m < 2) {
            __syncthreads();
            copyW(sW, ws[m+1], 2048, t);
            __syncthreads();
        }
    }
}

// ---------------------------------------------------------------------------
// Tensor-core GEMM using pre-split fragment-ordered weights.
// CTA: 128 rows x 128 cols. Warp w owns rows [16w, 16w+16), all 128 cols.
// smem sWb row pad x17 uint4 -> superbank = (grp+tig) mod 8: optimal 4-phase.
// Per nt per kt: ONE LDS.128 delivers (b0h,b1h,b0l,b1l).
// ---------------------------------------------------------------------------
__device__ __forceinline__ void tensor_gemm(
    float cc[16][4], int widx,
    const float* __restrict__ bias,
    const float* __restrict__ sH,
    uint4* __restrict__ sWb, int t)
{
    const int lane = t & 31, w = t >> 5;
    const int grp = lane >> 2, tig = lane & 3;
#pragma unroll
    for (int nt = 0; nt < 16; nt++) {
        int col = nt*8 + 2*tig;
        float b0 = bias[col], b1 = bias[col+1];
        cc[nt][0] = b0; cc[nt][1] = b1;
        cc[nt][2] = b0; cc[nt][3] = b1;
    }
    const float* aWarp = sH + (w*16)*HS;

#pragma unroll
    for (int q = 0; q < 4; q++) {
        __syncthreads();   // previous consumers of sWb done
        {
            const uint4* src = g_wfrag[widx][q];
            for (int o = t; o < 2048; o += 256)
                sWb[(o >> 4)*17 + (o & 15)] = src[o];
        }
        __syncthreads();

        const float* aq = aWarp + q*32;
#pragma unroll
        for (int kt = 0; kt < 4; kt++) {
            const float* ap = aq + grp*HS + kt*8 + tig;
            float r0 = ap[0];
            float r2 = ap[4];
            float r1 = ap[8*HS];
            float r3 = ap[8*HS + 4];
            unsigned a0h = tf32cvt(r0), a1h = tf32cvt(r1);
            unsigned a2h = tf32cvt(r2), a3h = tf32cvt(r3);
            unsigned a0l = tf32cvt(r0 - __uint_as_float(a0h));
            unsigned a1l = tf32cvt(r1 - __uint_as_float(a1h));
            unsigned a2l = tf32cvt(r2 - __uint_as_float(a2h));
            unsigned a3l = tf32cvt(r3 - __uint_as_float(a3h));
#pragma unroll
            for (int nt = 0; nt < 16; nt++) {
                uint4 bb = sWb[(nt*8 + grp)*17 + kt*4 + tig];
                MMA8(cc[nt], a0h,a1h,a2h,a3h, bb.x, bb.y);
                MMA8(cc[nt], a0l,a1l,a2l,a3l, bb.x, bb.y);
                MMA8(cc[nt], a0h,a1h,a2h,a3h, bb.z, bb.w);
            }
        }
    }
}

template<bool RELU>
__device__ __forceinline__ void tensor_store(float* __restrict__ sH,
                                             float cc[16][4], int t) {
    const int lane = t & 31, w = t >> 5;
    const int grp = lane >> 2, tig = lane & 3;
    int row0 = w*16 + grp;
#pragma unroll
    for (int nt = 0; nt < 16; nt++) {
        int col = nt*8 + 2*tig;
        float2 v0 = make_float2(cc[nt][0], cc[nt][1]);
        float2 v1 = make_float2(cc[nt][2], cc[nt][3]);
        if (RELU) {
            v0.x = fmaxf(v0.x, 0.f); v0.y = fmaxf(v0.y, 0.f);
            v1.x = fmaxf(v1.x, 0.f); v1.y = fmaxf(v1.y, 0.f);
        }
        *(float2*)(sH + row0*HS + col)     = v0;
        *(float2*)(sH + (row0+8)*HS + col) = v1;
    }
}
__device__ __forceinline__ void tensor_store_pos(float* __restrict__ sH,
                                                 float* __restrict__ posg,
                                                 float cc[16][4], int t) {
    const int lane = t & 31, w = t >> 5;
    const int grp = lane >> 2, tig = lane & 3;
    int row0 = w*16 + grp;
#pragma unroll
    for (int nt = 0; nt < 16; nt++) {
        int col = nt*8 + 2*tig;
        float2 v0 = make_float2(cc[nt][0], cc[nt][1]);
        float2 v1 = make_float2(cc[nt][2], cc[nt][3]);
        *(float2*)(sH + row0*HS + col)     = v0;
        *(float2*)(sH + (row0+8)*HS + col) = v1;
        *(float2*)(posg + (size_t)row0*128 + col)     = v0;
        *(float2*)(posg + (size_t)(row0+8)*128 + col) = v1;
    }
}

// ---------------------------------------------------------------------------
// Kernel 3: fused main, tensor-core GEMMs with pre-split weights.
// 8 nodes (128 rows)/CTA, 256 threads, 2048 CTAs, 2 CTAs/SM.
// ---------------------------------------------------------------------------
__global__ void __launch_bounds__(256, 2) main_kernel(
    const float* __restrict__ xyz, const float* __restrict__ features,
    const float* __restrict__ d1_w, const float* __restrict__ d1_b,
    const float* __restrict__ d2_w, const float* __restrict__ d2_b,
    const float* __restrict__ g1_w, const float* __restrict__ g1_b,
    const float* __restrict__ g2_w, const float* __restrict__ g2_b,
    const float* __restrict__ fc2_w, const float* __restrict__ fc2_b,
    float* __restrict__ out)
{
    extern __shared__ float sm[];
    uint4* sWb  = (uint4*)sm;                  // 2176 uint4 = 8704 floats
    float* sH   = sm + 8704;                   // 16896 (128 x 132)
    float* sRel = sm + 25600;                  // 384
    int*   sIdx = (int*)(sm + 25984);          // 128
    float* sRes = sm + 26112;                  // 1024 -> 27136 floats total

    int t = threadIdx.x;
    int g0 = blockIdx.x * 8;
    int bbase = g0 & ~(Nn - 1);
    float* posg = g_posbuf + (size_t)g0 * Kn * DM;

    // P0: idx + rel
    if (t < 128) {
        int j = g_idx[(size_t)g0*Kn + t];
        sIdx[t] = j;
        int nn = t >> 4;
        const float* pq = xyz + (size_t)(g0 + nn) * 3;
        const float* pj = xyz + (size_t)(bbase + j) * 3;
        sRel[t*3+0] = pq[0] - pj[0];
        sRel[t*3+1] = pq[1] - pj[1];
        sRel[t*3+2] = pq[2] - pj[2];
    }
    __syncthreads();

    // t1 = relu(rel@d1 + d1_b) -> sH (stride HS)
    for (int o4 = t; o4 < 4096; o4 += 256) {
        int r = o4 >> 5, c = (o4 & 31) * 4;
        float rx = sRel[r*3], ry = sRel[r*3+1], rz = sRel[r*3+2];
        float4 w0 = *(const float4*)(d1_w + c);
        float4 w1 = *(const float4*)(d1_w + 128 + c);
        float4 w2 = *(const float4*)(d1_w + 256 + c);
        float4 bb = *(const float4*)(d1_b + c);
        float4 v;
        v.x = fmaxf(fmaf(rz,w2.x,fmaf(ry,w1.x,fmaf(rx,w0.x,bb.x))), 0.f);
        v.y = fmaxf(fmaf(rz,w2.y,fmaf(ry,w1.y,fmaf(rx,w0.y,bb.y))), 0.f);
        v.z = fmaxf(fmaf(rz,w2.z,fmaf(ry,w1.z,fmaf(rx,w0.z,bb.z))), 0.f);
        v.w = fmaxf(fmaf(rz,w2.w,fmaf(ry,w1.w,fmaf(rx,w0.w,bb.w))), 0.f);
        *(float4*)(sH + r*HS + c) = v;
    }
    // (tensor_gemm starts with __syncthreads before staging)

    float cc[16][4];

    // pos = t1 @ d2 + d2_b
    tensor_gemm(cc, 0, d2_b, sH, sWb, t);
    tensor_store_pos(sH, posg, cc, t);     // own-stripe store
    __syncthreads();                        // h-phase reads all rows

    // h = q - k_gather + pos (in place)
    for (int o4 = t; o4 < 4096; o4 += 256) {
        int r = o4 >> 5, c = (o4 & 31) * 4;
        int nn = r >> 4;
        int j = sIdx[r];
        float4 kv = *(const float4*)(g_k + (size_t)(bbase + j)*128 + c);
        float4 qv = *(const float4*)(g_q + (size_t)(g0 + nn)*128 + c);
        float4 pv = *(const float4*)(sH + r*HS + c);
        float4 hh;
        hh.x = qv.x - kv.x + pv.x;
        hh.y = qv.y - kv.y + pv.y;
        hh.z = qv.z - kv.z + pv.z;
        hh.w = qv.w - kv.w + pv.w;
        *(float4*)(sH + r*HS + c) = hh;
    }
    __syncthreads();

    // a1 = relu(h @ g1 + g1_b)
    tensor_gemm(cc, 1, g1_b, sH, sWb, t);
    tensor_store<true>(sH, cc, t);          // own-stripe: no sync needed

    // logits = a1 @ g2 + g2_b
    tensor_gemm(cc, 2, g2_b, sH, sWb, t);
    tensor_store<false>(sH, cc, t);
    __syncthreads();                         // all mma done before sWb reuse

    // stage fc2 (8192 floats) into sWb region (contiguous at sm)
    copyW(sm, fc2_w, 2048, t);
    __syncthreads();

    // softmax over K; attn in place; res -> sRes
    for (int p = t; p < 1024; p += 256) {
        int nn = p >> 7, c = p & 127;
        int r0n = nn << 4;
        float m = -3.4e38f;
#pragma unroll
        for (int k = 0; k < Kn; k++) m = fmaxf(m, sH[(r0n+k)*HS + c]);
        float e[Kn];
        float ssum = 0.f;
#pragma unroll
        for (int k = 0; k < Kn; k++) {
            e[k] = __expf((sH[(r0n+k)*HS + c] - m) * SCALE_F);
            ssum += e[k];
        }
        float inv = 1.f / ssum;
        float racc = 0.f;
#pragma unroll
        for (int k = 0; k < Kn; k++) {
            float a = e[k] * inv;
            sH[(r0n+k)*HS + c] = a;
            int j = sIdx[r0n + k];
            float vp = g_v[(size_t)(bbase + j)*128 + c] + posg[(size_t)(r0n+k)*128 + c];
            racc = fmaf(a, vp, racc);
        }
        sRes[nn*128 + c] = racc;
    }
    __syncthreads();

    // attn out
    {
        float* attn_base = out + (size_t)ATT_OFF + (size_t)g0 * (Kn * DM);
        for (int o4 = t; o4 < 4096; o4 += 256) {
            int r = o4 >> 5, c = (o4 & 31) * 4;
            *(float4*)(attn_base + r*128 + c) = *(const float4*)(sH + r*HS + c);
        }
    }

    // out = res @ fc2 + fc2_b + pre  (fc2 = sm[0..8192))
    for (int p = t; p < 512; p += 256) {
        int nn = p >> 6, d = p & 63;
        float a0 = fc2_b[d] + features[(size_t)(g0 + nn)*64 + d];
        const float* rr2 = sRes + nn*128;
#pragma unroll 8
        for (int c = 0; c < 128; c++)
            a0 = fmaf(rr2[c], sm[c*64 + d], a0);
        out[(size_t)(g0 + nn)*64 + d] = a0;
    }
}

// ---------------------------------------------------------------------------
extern "C" void kernel_launch(void* const* d_in, const int* in_sizes, int n_in,
                              void* d_out, int out_size) {
    const float* xyz   = (const float*)d_in[0];
    const float* feats = (const float*)d_in[1];
    const float* fc1_w = (const float*)d_in[2];
    const float* fc1_b = (const float*)d_in[3];
    const float* fc2_w = (const float*)d_in[4];
    const float* fc2_b = (const float*)d_in[5];
    const float* d1_w  = (const float*)d_in[6];
    const float* d1_b  = (const float*)d_in[7];
    const float* d2_w  = (const float*)d_in[8];
    const float* d2_b  = (const float*)d_in[9];
    const float* g1_w  = (const float*)d_in[10];
    const float* g1_b  = (const float*)d_in[11];
    const float* g2_w  = (const float*)d_in[12];
    const float* g2_b  = (const float*)d_in[13];
    const float* wq    = (const float*)d_in[14];
    const float* wk    = (const float*)d_in[15];
    const float* wv    = (const float*)d_in[16];
    float* outp = (float*)d_out;

    const int SMEM_KNN  = 65536;             // 64 KB
    const int SMEM_PROJ = 24576 * 4;         // 98304 B
    const int SMEM_MAIN = 27136 * 4;         // 108544 B
    cudaFuncSetAttribute(knn_kernel,  cudaFuncAttributeMaxDynamicSharedMemorySize, SMEM_KNN);
    cudaFuncSetAttribute(proj_kernel, cudaFuncAttributeMaxDynamicSharedMemorySize, SMEM_PROJ);
    cudaFuncSetAttribute(main_kernel, cudaFuncAttributeMaxDynamicSharedMemorySize, SMEM_MAIN);

    sort_kernel<<<Bn, 1024>>>(xyz);
    wsplit_kernel<<<96, 256>>>(d2_w, g1_w, g2_w);
    knn_kernel<<<dim3(Nn/16, Bn), 512, SMEM_KNN>>>();
    proj_kernel<<<NODES/128, 256, SMEM_PROJ>>>(feats, fc1_w, fc1_b, wq, wk, wv);
    main_kernel<<<NODES/8, 256, SMEM_MAIN>>>(xyz, feats,
                                             d1_w, d1_b, d2_w, d2_b,
                                             g1_w, g1_b, g2_w, g2_b,
                                             fc2_w, fc2_b, outp);
}

// round 15
// speedup vs baseline: 1.0777x; 1.0777x over previous
#include <cuda_runtime.h>
#include <math.h>

// Problem constants
#define Bn 4
#define Nn 4096
#define Kn 16
#define DP 64
#define DM 128
#define NODES (Bn*Nn)            // 16384
#define ATT_OFF (NODES*DP)       // out region first, attn after
#define SCALE_F 0.08838834764831845f
#define FINF __int_as_float(0x7F800000)
#define KEY_INF 0xFFFFFFFFFFFFFFFFULL
#define HS 132                   // padded activation row stride (floats)
#define BS 36                    // transposed W stride (k per n-row, padded)

typedef unsigned long long ull;

// Scratch (device globals -- no allocation allowed)
__device__ int    g_idx[NODES*Kn];
__device__ float  g_q [NODES*DM];
__device__ float  g_k [NODES*DM];
__device__ float  g_v [NODES*DM];
__device__ float  g_posbuf[(size_t)NODES*Kn*DM];   // 128 MiB static scratch
__device__ float4 g_sp[NODES];                     // x-sorted (x,y,z,idx_bits)
__device__ float  g_zero[DM];                      // zero bias (static init)

// ---------------------------------------------------------------------------
// helpers
// ---------------------------------------------------------------------------
__device__ __forceinline__ ull pk2(float lo, float hi) {
    ull r;
    asm("mov.b64 %0, {%1,%2};" : "=l"(r)
        : "r"(__float_as_uint(lo)), "r"(__float_as_uint(hi)));
    return r;
}
__device__ __forceinline__ ull dup2f(float v) {
    ull r; unsigned u = __float_as_uint(v);
    asm("mov.b64 %0, {%1,%1};" : "=l"(r) : "r"(u));
    return r;
}
__device__ __forceinline__ void fma2(ull& d, ull a, ull b) {
    asm("fma.rn.f32x2 %0, %1, %2, %0;" : "+l"(d) : "l"(a), "l"(b));
}
__device__ __forceinline__ float2 up2(ull v) {
    unsigned lo, hi;
    asm("mov.b64 {%0,%1}, %2;" : "=r"(lo), "=r"(hi) : "l"(v));
    return make_float2(__uint_as_float(lo), __uint_as_float(hi));
}
__device__ __forceinline__ unsigned tf32cvt(float x) {
    unsigned r;
    asm("cvt.rna.tf32.f32 %0, %1;" : "=r"(r) : "f"(x));
    return r;
}
#define MMA8(c, a0,a1,a2,a3, b0,b1) \
    asm volatile("mma.sync.aligned.m16n8k8.row.col.f32.tf32.tf32.f32 " \
        "{%0,%1,%2,%3}, {%4,%5,%6,%7}, {%8,%9}, {%0,%1,%2,%3};" \
        : "+f"(c[0]), "+f"(c[1]), "+f"(c[2]), "+f"(c[3]) \
        : "r"(a0), "r"(a1), "r"(a2), "r"(a3), "r"(b0), "r"(b1))

// ---------------------------------------------------------------------------
// Kernel 0: per-batch bitonic sort of points by x. grid Bn x 1024 threads.
// ---------------------------------------------------------------------------
__global__ void __launch_bounds__(1024) sort_kernel(const float* __restrict__ xyz) {
    __shared__ float skey[Nn];
    __shared__ int   sval[Nn];
    int t = threadIdx.x;
    int b = blockIdx.x;
    const float* base = xyz + (size_t)b * Nn * 3;
    for (int i = t; i < Nn; i += 1024) { skey[i] = base[i*3]; sval[i] = i; }
    __syncthreads();
    for (int k = 2; k <= Nn; k <<= 1) {
        for (int j = k >> 1; j > 0; j >>= 1) {
            for (int e = t; e < Nn; e += 1024) {
                int p = e ^ j;
                if (p > e) {
                    bool up = ((e & k) == 0);
                    float a = skey[e], c = skey[p];
                    if ((a > c) == up) {
                        skey[e] = c; skey[p] = a;
                        int tv = sval[e]; sval[e] = sval[p]; sval[p] = tv;
                    }
                }
            }
            __syncthreads();
        }
    }
    for (int i = t; i < Nn; i += 1024) {
        int id = sval[i];
        g_sp[b*Nn + i] = make_float4(skey[i], base[id*3 + 1], base[id*3 + 2],
                                     __int_as_float(id));
    }
}

// ---------------------------------------------------------------------------
// Kernel 1: warp-per-query windowed KNN on x-sorted points (R9, proven).
// ---------------------------------------------------------------------------
__global__ void __launch_bounds__(512) knn_kernel() {
    extern __shared__ float4 spts[];       // 4096 * 16B = 65536
    int t = threadIdx.x;
    int b = blockIdx.y;
    for (int i = t; i < Nn; i += 512) spts[i] = g_sp[b*Nn + i];
    __syncthreads();

    const unsigned full = 0xffffffffu;
    int lane = t & 31;
    int r = blockIdx.x * 16 + (t >> 5);

    float4 me = spts[r];
    float qx = me.x, qy = me.y, qz = me.z;
    int qid = __float_as_int(me.w);

    ull key = KEY_INF;
    if (lane == 0) key = (unsigned)qid;
    ull wk = __shfl_sync(full, key, 15);

    bool isL = lane < 16;
    int lo = r - 1, hi = r + 1;
    bool aliveL = true, aliveR = true;

    while (aliveL || aliveR) {
        ull  ckey = KEY_INF;
        float dxx = FINF;
        bool inr = false;
        int cand = isL ? (lo - lane) : (hi + (lane - 16));
        if (isL) inr = aliveL && (cand >= 0);
        else     inr = aliveR && (cand < Nn);
        if (inr) {
            float4 p = spts[cand];
            float dx = qx - p.x, dy = qy - p.y, dz = qz - p.z;
            dxx = __fmul_rn(dx, dx);
            float d = __fadd_rn(__fadd_rn(dxx, __fmul_rn(dy,dy)),
                                __fmul_rn(dz,dz));
            ckey = ((ull)__float_as_uint(d) << 32) |
                   (unsigned)__float_as_int(p.w);
        }

        unsigned ball = __ballot_sync(full, inr && ckey < wk);
        while (ball) {
            int s = __ffs(ball) - 1; ball &= ball - 1;
            ull k = __shfl_sync(full, ckey, s);
            if (k >= wk) continue;
            unsigned bl = __ballot_sync(full, isL && key < k);
            int pos = __popc(bl);
            ull up = __shfl_up_sync(full, key, 1);
            if (isL) {
                if (lane == pos) key = k;
                else if (lane > pos) key = up;
            }
            wk = __shfl_sync(full, key, 15);
        }

        float worstd = __uint_as_float((unsigned)(wk >> 32));
        float dxx15 = __shfl_sync(full, dxx, 15);
        float dxx31 = __shfl_sync(full, dxx, 31);
        int   inr15 = __shfl_sync(full, (int)inr, 15);
        int   inr31 = __shfl_sync(full, (int)inr, 31);
        aliveL = aliveL && inr15 && !(dxx15 > worstd);
        aliveR = aliveR && inr31 && !(dxx31 > worstd);
        lo -= 16; hi += 16;
    }

    if (isL)
        g_idx[((size_t)b*Nn + qid) * Kn + lane] =
            (int)(unsigned)(key & 0xffffffffu);
}

// ---------------------------------------------------------------------------
// Scalar f32x2 GEMM helpers (fc1 in proj)
// ---------------------------------------------------------------------------
template<int KD, int AS>
__device__ __forceinline__ void gemm_r8(ull acc[8][4],
                                        const float* __restrict__ sA,
                                        const float* __restrict__ sW, int t) {
    const int c0 = (t & 15) * 8;
    const int r0 = (t >> 4) * 8;
#pragma unroll 2
    for (int kk = 0; kk < KD; kk += 4) {
        float4 a4[8];
#pragma unroll
        for (int i = 0; i < 8; i++)
            a4[i] = *(const float4*)(sA + (r0 + i) * AS + kk);
#pragma unroll
        for (int kq = 0; kq < 4; kq++) {
            const float* wr = sW + (kk + kq) * 128 + c0;
            ulonglong2 wl = *(const ulonglong2*)(wr);
            ulonglong2 wh = *(const ulonglong2*)(wr + 4);
#pragma unroll
            for (int i = 0; i < 8; i++) {
                float av = (kq == 0) ? a4[i].x : (kq == 1) ? a4[i].y
                         : (kq == 2) ? a4[i].z : a4[i].w;
                ull ad = dup2f(av);
                fma2(acc[i][0], ad, wl.x);
                fma2(acc[i][1], ad, wl.y);
                fma2(acc[i][2], ad, wh.x);
                fma2(acc[i][3], ad, wh.y);
            }
        }
    }
}
__device__ __forceinline__ void init_r8(ull acc[8][4], const float* __restrict__ bias, int t) {
    const int c0 = (t & 15) * 8;
#pragma unroll
    for (int j = 0; j < 4; j++) {
        ull b2 = pk2(bias[c0 + 2*j], bias[c0 + 2*j + 1]);
#pragma unroll
        for (int i = 0; i < 8; i++) acc[i][j] = b2;
    }
}
template<bool RELU>
__device__ __forceinline__ void store_r8(float* __restrict__ dst, int stride,
                                         ull acc[8][4], int t) {
    const int c0 = (t & 15) * 8;
    const int r0 = (t >> 4) * 8;
#pragma unroll
    for (int i = 0; i < 8; i++) {
        float2 p0 = up2(acc[i][0]), p1 = up2(acc[i][1]);
        float2 p2 = up2(acc[i][2]), p3 = up2(acc[i][3]);
        float4 lo = make_float4(p0.x, p0.y, p1.x, p1.y);
        float4 hi = make_float4(p2.x, p2.y, p3.x, p3.y);
        if (RELU) {
            lo.x = fmaxf(lo.x, 0.f); lo.y = fmaxf(lo.y, 0.f);
            lo.z = fmaxf(lo.z, 0.f); lo.w = fmaxf(lo.w, 0.f);
            hi.x = fmaxf(hi.x, 0.f); hi.y = fmaxf(hi.y, 0.f);
            hi.z = fmaxf(hi.z, 0.f); hi.w = fmaxf(hi.w, 0.f);
        }
        *(float4*)(dst + (size_t)(r0 + i) * stride + c0)     = lo;
        *(float4*)(dst + (size_t)(r0 + i) * stride + c0 + 4) = hi;
    }
}
__device__ __forceinline__ void copyW(float* __restrict__ dst,
                                      const float* __restrict__ src, int n4, int t) {
    for (int o = t; o < n4; o += 256)
        *(float4*)(dst + o*4) = *(const float4*)(src + o*4);
}

// ---------------------------------------------------------------------------
// Tensor-core GEMM (tf32 mma.sync, 3xTF32 split) -- R13 version with
// improved staging: per thread 4 tasks of (n, 4 consecutive k):
// coalesced LDG + STS.128, conflict-free ((9n+kb) mod 8 spreads lanes).
// Mainloop b-frag LDS.32 pattern unchanged (proven conflict-free).
// ---------------------------------------------------------------------------
__device__ __forceinline__ void tensor_gemm(
    float cc[16][4], const float* __restrict__ Wg,
    const float* __restrict__ bias,
    const float* __restrict__ sA,
    unsigned* __restrict__ sWhi, unsigned* __restrict__ sWlo, int t)
{
    const int lane = t & 31, w = t >> 5;
    const int grp = lane >> 2, tig = lane & 3;
#pragma unroll
    for (int nt = 0; nt < 16; nt++) {
        int col = nt*8 + 2*tig;
        float b0 = bias[col], b1 = bias[col+1];
        cc[nt][0] = b0; cc[nt][1] = b1;
        cc[nt][2] = b0; cc[nt][3] = b1;
    }
    const float* aWarp = sA + (w*16)*HS;

#pragma unroll
    for (int q = 0; q < 4; q++) {
        __syncthreads();   // previous consumers of sW done
        // stage quarter q: split + transpose, STS.128, conflict-free
        for (int o = t; o < 1024; o += 256) {
            int n = o & 127, kb = o >> 7;          // kb: 0..7 (4-k blocks)
            const float* src = Wg + q*4096 + (kb*4)*128 + n;
            float x0 = src[0];
            float x1 = src[128];
            float x2 = src[256];
            float x3 = src[384];
            unsigned h0 = tf32cvt(x0), h1 = tf32cvt(x1);
            unsigned h2 = tf32cvt(x2), h3 = tf32cvt(x3);
            uint4 hv = make_uint4(h0, h1, h2, h3);
            uint4 lv = make_uint4(tf32cvt(x0 - __uint_as_float(h0)),
                                  tf32cvt(x1 - __uint_as_float(h1)),
                                  tf32cvt(x2 - __uint_as_float(h2)),
                                  tf32cvt(x3 - __uint_as_float(h3)));
            *(uint4*)(sWhi + n*BS + kb*4) = hv;
            *(uint4*)(sWlo + n*BS + kb*4) = lv;
        }
        __syncthreads();

        const float* aq = aWarp + q*32;
#pragma unroll
        for (int kt = 0; kt < 4; kt++) {
            const float* ap = aq + grp*HS + kt*8 + tig;
            float r0 = ap[0];
            float r2 = ap[4];
            float r1 = ap[8*HS];
            float r3 = ap[8*HS + 4];
            unsigned a0h = tf32cvt(r0), a1h = tf32cvt(r1);
            unsigned a2h = tf32cvt(r2), a3h = tf32cvt(r3);
            unsigned a0l = tf32cvt(r0 - __uint_as_float(a0h));
            unsigned a1l = tf32cvt(r1 - __uint_as_float(a1h));
            unsigned a2l = tf32cvt(r2 - __uint_as_float(a2h));
            unsigned a3l = tf32cvt(r3 - __uint_as_float(a3h));
#pragma unroll
            for (int nt = 0; nt < 16; nt++) {
                const unsigned* bh = sWhi + (nt*8 + grp)*BS + kt*8 + tig;
                const unsigned* bl = sWlo + (nt*8 + grp)*BS + kt*8 + tig;
                unsigned b0h = bh[0], b1h = bh[4];
                unsigned b0l = bl[0], b1l = bl[4];
                MMA8(cc[nt], a0h,a1h,a2h,a3h, b0h,b1h);
                MMA8(cc[nt], a0l,a1l,a2l,a3l, b0h,b1h);
                MMA8(cc[nt], a0h,a1h,a2h,a3h, b0l,b1l);
            }
        }
    }
}

template<bool RELU>
__device__ __forceinline__ void tensor_store(float* __restrict__ dst, int S,
                                             float cc[16][4], int t) {
    const int lane = t & 31, w = t >> 5;
    const int grp = lane >> 2, tig = lane & 3;
    int row0 = w*16 + grp;
#pragma unroll
    for (int nt = 0; nt < 16; nt++) {
        int col = nt*8 + 2*tig;
        float2 v0 = make_float2(cc[nt][0], cc[nt][1]);
        float2 v1 = make_float2(cc[nt][2], cc[nt][3]);
        if (RELU) {
            v0.x = fmaxf(v0.x, 0.f); v0.y = fmaxf(v0.y, 0.f);
            v1.x = fmaxf(v1.x, 0.f); v1.y = fmaxf(v1.y, 0.f);
        }
        *(float2*)(dst + (size_t)row0 * S + col)     = v0;
        *(float2*)(dst + (size_t)(row0+8) * S + col) = v1;
    }
}
__device__ __forceinline__ void tensor_store_pos(float* __restrict__ sH,
                                                 float* __restrict__ posg,
                                                 float cc[16][4], int t) {
    const int lane = t & 31, w = t >> 5;
    const int grp = lane >> 2, tig = lane & 3;
    int row0 = w*16 + grp;
#pragma unroll
    for (int nt = 0; nt < 16; nt++) {
        int col = nt*8 + 2*tig;
        float2 v0 = make_float2(cc[nt][0], cc[nt][1]);
        float2 v1 = make_float2(cc[nt][2], cc[nt][3]);
        *(float2*)(sH + row0*HS + col)     = v0;
        *(float2*)(sH + (row0+8)*HS + col) = v1;
        *(float2*)(posg + (size_t)row0*128 + col)     = v0;
        *(float2*)(posg + (size_t)(row0+8)*128 + col) = v1;
    }
}

// ---------------------------------------------------------------------------
// Kernel 2: fused projections, tensor q/k/v. 128 rows/CTA, 256 thr, grid 128.
// smem: sWhi/sWlo (9216 floats) + sX (16896) = 26112 floats (104448 B).
// ---------------------------------------------------------------------------
__global__ void __launch_bounds__(256, 2) proj_kernel(
    const float* __restrict__ feats,
    const float* __restrict__ fc1_w, const float* __restrict__ fc1_b,
    const float* __restrict__ wq, const float* __restrict__ wk,
    const float* __restrict__ wv)
{
    extern __shared__ float sm2[];
    unsigned* sWhi = (unsigned*)sm2;           // 4608
    unsigned* sWlo = (unsigned*)(sm2 + 4608);  // 4608
    float* sX = sm2 + 9216;                    // 16896 (128 x HS)
    int t = threadIdx.x;
    int g0 = blockIdx.x * 128;

    // fc1 (scalar): feats 128x64 at stride 64 in sX; fc1_w in sWhi region
    copyW(sX, feats + (size_t)g0*64, 2048, t);
    copyW((float*)sWhi, fc1_w, 2048, t);
    __syncthreads();

    ull acc[8][4];
    init_r8(acc, fc1_b, t);
    gemm_r8<64, 64>(acc, sX, (float*)sWhi, t);
    __syncthreads();                 // all reads of sX done
    store_r8<false>(sX, HS, acc, t); // x re-laid at stride HS

    float cc[16][4];
    // q/k/v = x @ {wq,wk,wv} (tensor; tensor_gemm syncs before staging)
    tensor_gemm(cc, wq, g_zero, sX, sWhi, sWlo, t);
    tensor_store<false>(g_q + (size_t)g0*128, 128, cc, t);
    tensor_gemm(cc, wk, g_zero, sX, sWhi, sWlo, t);
    tensor_store<false>(g_k + (size_t)g0*128, 128, cc, t);
    tensor_gemm(cc, wv, g_zero, sX, sWhi, sWlo, t);
    tensor_store<false>(g_v + (size_t)g0*128, 128, cc, t);
}

// ---------------------------------------------------------------------------
// Kernel 3: fused main, tensor-core GEMMs (R13 structure).
// 8 nodes (128 rows)/CTA, 256 threads, 2048 CTAs, 2 CTAs/SM.
// ---------------------------------------------------------------------------
__global__ void __launch_bounds__(256, 2) main_kernel(
    const float* __restrict__ xyz, const float* __restrict__ features,
    const float* __restrict__ d1_w, const float* __restrict__ d1_b,
    const float* __restrict__ d2_w, const float* __restrict__ d2_b,
    const float* __restrict__ g1_w, const float* __restrict__ g1_b,
    const float* __restrict__ g2_w, const float* __restrict__ g2_b,
    const float* __restrict__ fc2_w, const float* __restrict__ fc2_b,
    float* __restrict__ out)
{
    extern __shared__ float sm[];
    unsigned* sWhi = (unsigned*)sm;            // 4608
    unsigned* sWlo = (unsigned*)(sm + 4608);   // 4608
    float* sH   = sm + 9216;                   // 16896 (128 x 132)
    float* sRel = sm + 26112;                  // 384
    int*   sIdx = (int*)(sm + 26496);          // 128
    float* sRes = sm + 26624;                  // 1024 -> 27648 floats total

    int t = threadIdx.x;
    int g0 = blockIdx.x * 8;
    int bbase = g0 & ~(Nn - 1);
    float* posg = g_posbuf + (size_t)g0 * Kn * DM;

    // P0: idx + rel
    if (t < 128) {
        int j = g_idx[(size_t)g0*Kn + t];
        sIdx[t] = j;
        int nn = t >> 4;
        const float* pq = xyz + (size_t)(g0 + nn) * 3;
        const float* pj = xyz + (size_t)(bbase + j) * 3;
        sRel[t*3+0] = pq[0] - pj[0];
        sRel[t*3+1] = pq[1] - pj[1];
        sRel[t*3+2] = pq[2] - pj[2];
    }
    __syncthreads();

    // t1 = relu(rel@d1 + d1_b) -> sH (stride HS)
    for (int o4 = t; o4 < 4096; o4 += 256) {
        int r = o4 >> 5, c = (o4 & 31) * 4;
        float rx = sRel[r*3], ry = sRel[r*3+1], rz = sRel[r*3+2];
        float4 w0 = *(const float4*)(d1_w + c);
        float4 w1 = *(const float4*)(d1_w + 128 + c);
        float4 w2 = *(const float4*)(d1_w + 256 + c);
        float4 bb = *(const float4*)(d1_b + c);
        float4 v;
        v.x = fmaxf(fmaf(rz,w2.x,fmaf(ry,w1.x,fmaf(rx,w0.x,bb.x))), 0.f);
        v.y = fmaxf(fmaf(rz,w2.y,fmaf(ry,w1.y,fmaf(rx,w0.y,bb.y))), 0.f);
        v.z = fmaxf(fmaf(rz,w2.z,fmaf(ry,w1.z,fmaf(rx,w0.z,bb.z))), 0.f);
        v.w = fmaxf(fmaf(rz,w2.w,fmaf(ry,w1.w,fmaf(rx,w0.w,bb.w))), 0.f);
        *(float4*)(sH + r*HS + c) = v;
    }
    // (tensor_gemm starts with __syncthreads before staging)

    float cc[16][4];

    // pos = t1 @ d2 + d2_b
    tensor_gemm(cc, d2_w, d2_b, sH, sWhi, sWlo, t);
    tensor_store_pos(sH, posg, cc, t);     // own-stripe store
    __syncthreads();                        // h-phase reads all rows

    // h = q - k_gather + pos (in place)
    for (int o4 = t; o4 < 4096; o4 += 256) {
        int r = o4 >> 5, c = (o4 & 31) * 4;
        int nn = r >> 4;
        int j = sIdx[r];
        float4 kv = *(const float4*)(g_k + (size_t)(bbase + j)*128 + c);
        float4 qv = *(const float4*)(g_q + (size_t)(g0 + nn)*128 + c);
        float4 pv = *(const float4*)(sH + r*HS + c);
        float4 hh;
        hh.x = qv.x - kv.x + pv.x;
        hh.y = qv.y - kv.y + pv.y;
        hh.z = qv.z - kv.z + pv.z;
        hh.w = qv.w - kv.w + pv.w;
        *(float4*)(sH + r*HS + c) = hh;
    }
    __syncthreads();

    // a1 = relu(h @ g1 + g1_b)
    tensor_gemm(cc, g1_w, g1_b, sH, sWhi, sWlo, t);
    tensor_store<true>(sH, HS, cc, t);      // own-stripe: no sync needed

    // logits = a1 @ g2 + g2_b
    tensor_gemm(cc, g2_w, g2_b, sH, sWhi, sWlo, t);
    tensor_store<false>(sH, HS, cc, t);
    __syncthreads();                         // all mma done before sW reuse

    // stage fc2 (8192 floats) into sWhi..sWlo region (contiguous at sm)
    copyW(sm, fc2_w, 2048, t);
    __syncthreads();

    // softmax over K; attn in place; res -> sRes
    for (int p = t; p < 1024; p += 256) {
        int nn = p >> 7, c = p & 127;
        int r0n = nn << 4;
        float m = -3.4e38f;
#pragma unroll
        for (int k = 0; k < Kn; k++) m = fmaxf(m, sH[(r0n+k)*HS + c]);
        float e[Kn];
        float ssum = 0.f;
#pragma unroll
        for (int k = 0; k < Kn; k++) {
            e[k] = __expf((sH[(r0n+k)*HS + c] - m) * SCALE_F);
            ssum += e[k];
        }
        float inv = 1.f / ssum;
        float racc = 0.f;
#pragma unroll
        for (int k = 0; k < Kn; k++) {
            float a = e[k] * inv;
            sH[(r0n+k)*HS + c] = a;
            int j = sIdx[r0n + k];
            float vp = g_v[(size_t)(bbase + j)*128 + c] + posg[(size_t)(r0n+k)*128 + c];
            racc = fmaf(a, vp, racc);
        }
        sRes[nn*128 + c] = racc;
    }
    __syncthreads();

    // attn out
    {
        float* attn_base = out + (size_t)ATT_OFF + (size_t)g0 * (Kn * DM);
        for (int o4 = t; o4 < 4096; o4 += 256) {
            int r = o4 >> 5, c = (o4 & 31) * 4;
            *(float4*)(attn_base + r*128 + c) = *(const float4*)(sH + r*HS + c);
        }
    }

    // out = res @ fc2 + fc2_b + pre  (fc2 = sm[0..8192))
    for (int p = t; p < 512; p += 256) {
        int nn = p >> 6, d = p & 63;
        float a0 = fc2_b[d] + features[(size_t)(g0 + nn)*64 + d];
        const float* rr2 = sRes + nn*128;
#pragma unroll 8
        for (int c = 0; c < 128; c++)
            a0 = fmaf(rr2[c], sm[c*64 + d], a0);
        out[(size_t)(g0 + nn)*64 + d] = a0;
    }
}

// ---------------------------------------------------------------------------
extern "C" void kernel_launch(void* const* d_in, const int* in_sizes, int n_in,
                              void* d_out, int out_size) {
    const float* xyz   = (const float*)d_in[0];
    const float* feats = (const float*)d_in[1];
    const float* fc1_w = (const float*)d_in[2];
    const float* fc1_b = (const float*)d_in[3];
    const float* fc2_w = (const float*)d_in[4];
    const float* fc2_b = (const float*)d_in[5];
    const float* d1_w  = (const float*)d_in[6];
    const float* d1_b  = (const float*)d_in[7];
    const float* d2_w  = (const float*)d_in[8];
    const float* d2_b  = (const float*)d_in[9];
    const float* g1_w  = (const float*)d_in[10];
    const float* g1_b  = (const float*)d_in[11];
    const float* g2_w  = (const float*)d_in[12];
    const float* g2_b  = (const float*)d_in[13];
    const float* wq    = (const float*)d_in[14];
    const float* wk    = (const float*)d_in[15];
    const float* wv    = (const float*)d_in[16];
    float* outp = (float*)d_out;

    const int SMEM_KNN  = 65536;             // 64 KB
    const int SMEM_PROJ = 26112 * 4;         // 104448 B
    const int SMEM_MAIN = 27648 * 4;         // 110592 B
    cudaFuncSetAttribute(knn_kernel,  cudaFuncAttributeMaxDynamicSharedMemorySize, SMEM_KNN);
    cudaFuncSetAttribute(proj_kernel, cudaFuncAttributeMaxDynamicSharedMemorySize, SMEM_PROJ);
    cudaFuncSetAttribute(main_kernel, cudaFuncAttributeMaxDynamicSharedMemorySize, SMEM_MAIN);

    sort_kernel<<<Bn, 1024>>>(xyz);
    knn_kernel<<<dim3(Nn/16, Bn), 512, SMEM_KNN>>>();
    proj_kernel<<<NODES/128, 256, SMEM_PROJ>>>(feats, fc1_w, fc1_b, wq, wk, wv);
    main_kernel<<<NODES/8, 256, SMEM_MAIN>>>(xyz, feats,
                                             d1_w, d1_b, d2_w, d2_b,
                                             g1_w, g1_b, g2_w, g2_b,
                                             fc2_w, fc2_b, outp);
}

// round 16
// speedup vs baseline: 1.0973x; 1.0182x over previous
#include <cuda_runtime.h>
#include <math.h>

// Problem constants
#define Bn 4
#define Nn 4096
#define Kn 16
#define DP 64
#define DM 128
#define NODES (Bn*Nn)            // 16384
#define ATT_OFF (NODES*DP)       // out region first, attn after
#define SCALE_F 0.08838834764831845f
#define FINF __int_as_float(0x7F800000)
#define KEY_INF 0xFFFFFFFFFFFFFFFFULL
#define HS 132                   // padded activation row stride (floats)
#define BS 36                    // transposed W stride (k per n-row, padded)

typedef unsigned long long ull;

// Scratch (device globals -- no allocation allowed)
__device__ int    g_idx[NODES*Kn];
__device__ float  g_q [NODES*DM];
__device__ float  g_k [NODES*DM];
__device__ float  g_v [NODES*DM];
__device__ float  g_posbuf[(size_t)NODES*Kn*DM];   // 128 MiB static scratch
__device__ float4 g_sp[NODES];                     // x-sorted (x,y,z,idx_bits)
__device__ float  g_zero[DM];                      // zero bias (static init)
// Pre-split tf32 weights, packed per quarter [w][q*4096 + n*32 + kk]
// w: 0=d2 1=g1 2=g2 3=wq 4=wk 5=wv
__device__ unsigned g_whi[6][4*4096];
__device__ unsigned g_wlo[6][4*4096];

// ---------------------------------------------------------------------------
// helpers
// ---------------------------------------------------------------------------
__device__ __forceinline__ ull pk2(float lo, float hi) {
    ull r;
    asm("mov.b64 %0, {%1,%2};" : "=l"(r)
        : "r"(__float_as_uint(lo)), "r"(__float_as_uint(hi)));
    return r;
}
__device__ __forceinline__ ull dup2f(float v) {
    ull r; unsigned u = __float_as_uint(v);
    asm("mov.b64 %0, {%1,%1};" : "=l"(r) : "r"(u));
    return r;
}
__device__ __forceinline__ void fma2(ull& d, ull a, ull b) {
    asm("fma.rn.f32x2 %0, %1, %2, %0;" : "+l"(d) : "l"(a), "l"(b));
}
__device__ __forceinline__ float2 up2(ull v) {
    unsigned lo, hi;
    asm("mov.b64 {%0,%1}, %2;" : "=r"(lo), "=r"(hi) : "l"(v));
    return make_float2(__uint_as_float(lo), __uint_as_float(hi));
}
__device__ __forceinline__ unsigned tf32cvt(float x) {
    unsigned r;
    asm("cvt.rna.tf32.f32 %0, %1;" : "=r"(r) : "f"(x));
    return r;
}
#define MMA8(c, a0,a1,a2,a3, b0,b1) \
    asm volatile("mma.sync.aligned.m16n8k8.row.col.f32.tf32.tf32.f32 " \
        "{%0,%1,%2,%3}, {%4,%5,%6,%7}, {%8,%9}, {%0,%1,%2,%3};" \
        : "+f"(c[0]), "+f"(c[1]), "+f"(c[2]), "+f"(c[3]) \
        : "r"(a0), "r"(a1), "r"(a2), "r"(a3), "r"(b0), "r"(b1))

// ---------------------------------------------------------------------------
// Kernel 0a: per-batch bitonic sort of points by x. grid Bn x 1024 threads.
// ---------------------------------------------------------------------------
__global__ void __launch_bounds__(1024) sort_kernel(const float* __restrict__ xyz) {
    __shared__ float skey[Nn];
    __shared__ int   sval[Nn];
    int t = threadIdx.x;
    int b = blockIdx.x;
    const float* base = xyz + (size_t)b * Nn * 3;
    for (int i = t; i < Nn; i += 1024) { skey[i] = base[i*3]; sval[i] = i; }
    __syncthreads();
    for (int k = 2; k <= Nn; k <<= 1) {
        for (int j = k >> 1; j > 0; j >>= 1) {
            for (int e = t; e < Nn; e += 1024) {
                int p = e ^ j;
                if (p > e) {
                    bool up = ((e & k) == 0);
                    float a = skey[e], c = skey[p];
                    if ((a > c) == up) {
                        skey[e] = c; skey[p] = a;
                        int tv = sval[e]; sval[e] = sval[p]; sval[p] = tv;
                    }
                }
            }
            __syncthreads();
        }
    }
    for (int i = t; i < Nn; i += 1024) {
        int id = sval[i];
        g_sp[b*Nn + i] = make_float4(skey[i], base[id*3 + 1], base[id*3 + 2],
                                     __int_as_float(id));
    }
}

// ---------------------------------------------------------------------------
// Kernel 0b: pre-split six 128x128 weights into tf32 hi/lo, packed
// [w][q*4096 + n*32 + kk] (quarter q, output col n, k = q*32+kk).
// grid 384 x 256 (one element per thread).
// ---------------------------------------------------------------------------
__global__ void __launch_bounds__(256) wsplit_kernel(
    const float* __restrict__ d2, const float* __restrict__ g1,
    const float* __restrict__ g2, const float* __restrict__ wq,
    const float* __restrict__ wk, const float* __restrict__ wv)
{
    int gid = blockIdx.x * 256 + threadIdx.x;   // 0..98303
    int w   = gid >> 14;                        // 6 weights x 16384 each
    int e   = gid & 16383;
    int q   = e >> 12;
    int r   = e & 4095;
    int n   = r >> 5;
    int kk  = r & 31;
    const float* W = (w == 0) ? d2 : (w == 1) ? g1 : (w == 2) ? g2
                   : (w == 3) ? wq : (w == 4) ? wk : wv;
    float x = W[(size_t)(q*32 + kk) * 128 + n];
    unsigned h = tf32cvt(x);
    g_whi[w][e] = h;
    g_wlo[w][e] = tf32cvt(x - __uint_as_float(h));
}

// ---------------------------------------------------------------------------
// Kernel 1: warp-per-query windowed KNN on x-sorted points (R9, proven).
// ---------------------------------------------------------------------------
__global__ void __launch_bounds__(512) knn_kernel() {
    extern __shared__ float4 spts[];       // 4096 * 16B = 65536
    int t = threadIdx.x;
    int b = blockIdx.y;
    for (int i = t; i < Nn; i += 512) spts[i] = g_sp[b*Nn + i];
    __syncthreads();

    const unsigned full = 0xffffffffu;
    int lane = t & 31;
    int r = blockIdx.x * 16 + (t >> 5);

    float4 me = spts[r];
    float qx = me.x, qy = me.y, qz = me.z;
    int qid = __float_as_int(me.w);

    ull key = KEY_INF;
    if (lane == 0) key = (unsigned)qid;
    ull wk = __shfl_sync(full, key, 15);

    bool isL = lane < 16;
    int lo = r - 1, hi = r + 1;
    bool aliveL = true, aliveR = true;

    while (aliveL || aliveR) {
        ull  ckey = KEY_INF;
        float dxx = FINF;
        bool inr = false;
        int cand = isL ? (lo - lane) : (hi + (lane - 16));
        if (isL) inr = aliveL && (cand >= 0);
        else     inr = aliveR && (cand < Nn);
        if (inr) {
            float4 p = spts[cand];
            float dx = qx - p.x, dy = qy - p.y, dz = qz - p.z;
            dxx = __fmul_rn(dx, dx);
            float d = __fadd_rn(__fadd_rn(dxx, __fmul_rn(dy,dy)),
                                __fmul_rn(dz,dz));
            ckey = ((ull)__float_as_uint(d) << 32) |
                   (unsigned)__float_as_int(p.w);
        }

        unsigned ball = __ballot_sync(full, inr && ckey < wk);
        while (ball) {
            int s = __ffs(ball) - 1; ball &= ball - 1;
            ull k = __shfl_sync(full, ckey, s);
            if (k >= wk) continue;
            unsigned bl = __ballot_sync(full, isL && key < k);
            int pos = __popc(bl);
            ull up = __shfl_up_sync(full, key, 1);
            if (isL) {
                if (lane == pos) key = k;
                else if (lane > pos) key = up;
            }
            wk = __shfl_sync(full, key, 15);
        }

        float worstd = __uint_as_float((unsigned)(wk >> 32));
        float dxx15 = __shfl_sync(full, dxx, 15);
        float dxx31 = __shfl_sync(full, dxx, 31);
        int   inr15 = __shfl_sync(full, (int)inr, 15);
        int   inr31 = __shfl_sync(full, (int)inr, 31);
        aliveL = aliveL && inr15 && !(dxx15 > worstd);
        aliveR = aliveR && inr31 && !(dxx31 > worstd);
        lo -= 16; hi += 16;
    }

    if (isL)
        g_idx[((size_t)b*Nn + qid) * Kn + lane] =
            (int)(unsigned)(key & 0xffffffffu);
}

// ---------------------------------------------------------------------------
// Scalar f32x2 GEMM helpers (fc1 in proj)
// ---------------------------------------------------------------------------
template<int KD, int AS>
__device__ __forceinline__ void gemm_r8(ull acc[8][4],
                                        const float* __restrict__ sA,
                                        const float* __restrict__ sW, int t) {
    const int c0 = (t & 15) * 8;
    const int r0 = (t >> 4) * 8;
#pragma unroll 2
    for (int kk = 0; kk < KD; kk += 4) {
        float4 a4[8];
#pragma unroll
        for (int i = 0; i < 8; i++)
            a4[i] = *(const float4*)(sA + (r0 + i) * AS + kk);
#pragma unroll
        for (int kq = 0; kq < 4; kq++) {
            const float* wr = sW + (kk + kq) * 128 + c0;
            ulonglong2 wl = *(const ulonglong2*)(wr);
            ulonglong2 wh = *(const ulonglong2*)(wr + 4);
#pragma unroll
            for (int i = 0; i < 8; i++) {
                float av = (kq == 0) ? a4[i].x : (kq == 1) ? a4[i].y
                         : (kq == 2) ? a4[i].z : a4[i].w;
                ull ad = dup2f(av);
                fma2(acc[i][0], ad, wl.x);
                fma2(acc[i][1], ad, wl.y);
                fma2(acc[i][2], ad, wh.x);
                fma2(acc[i][3], ad, wh.y);
            }
        }
    }
}
__device__ __forceinline__ void init_r8(ull acc[8][4], const float* __restrict__ bias, int t) {
    const int c0 = (t & 15) * 8;
#pragma unroll
    for (int j = 0; j < 4; j++) {
        ull b2 = pk2(bias[c0 + 2*j], bias[c0 + 2*j + 1]);
#pragma unroll
        for (int i = 0; i < 8; i++) acc[i][j] = b2;
    }
}
template<bool RELU>
__device__ __forceinline__ void store_r8(float* __restrict__ dst, int stride,
                                         ull acc[8][4], int t) {
    const int c0 = (t & 15) * 8;
    const int r0 = (t >> 4) * 8;
#pragma unroll
    for (int i = 0; i < 8; i++) {
        float2 p0 = up2(acc[i][0]), p1 = up2(acc[i][1]);
        float2 p2 = up2(acc[i][2]), p3 = up2(acc[i][3]);
        float4 lo = make_float4(p0.x, p0.y, p1.x, p1.y);
        float4 hi = make_float4(p2.x, p2.y, p3.x, p3.y);
        if (RELU) {
            lo.x = fmaxf(lo.x, 0.f); lo.y = fmaxf(lo.y, 0.f);
            lo.z = fmaxf(lo.z, 0.f); lo.w = fmaxf(lo.w, 0.f);
            hi.x = fmaxf(hi.x, 0.f); hi.y = fmaxf(hi.y, 0.f);
            hi.z = fmaxf(hi.z, 0.f); hi.w = fmaxf(hi.w, 0.f);
        }
        *(float4*)(dst + (size_t)(r0 + i) * stride + c0)     = lo;
        *(float4*)(dst + (size_t)(r0 + i) * stride + c0 + 4) = hi;
    }
}
__device__ __forceinline__ void copyW(float* __restrict__ dst,
                                      const float* __restrict__ src, int n4, int t) {
    for (int o = t; o < n4; o += 256)
        *(float4*)(dst + o*4) = *(const float4*)(src + o*4);
}

// ---------------------------------------------------------------------------
// Tensor-core GEMM (tf32 mma.sync, 3xTF32 split). Mainloop identical to R15.
// Staging is now a PURE COPY from pre-split g_whi/g_wlo (coalesced LDG.128,
// STS.128 into the same BS=36 layout). No cvt in the hot path for weights.
// ---------------------------------------------------------------------------
__device__ __forceinline__ void tensor_gemm(
    float cc[16][4], int widx,
    const float* __restrict__ bias,
    const float* __restrict__ sA,
    unsigned* __restrict__ sWhi, unsigned* __restrict__ sWlo, int t)
{
    const int lane = t & 31, w = t >> 5;
    const int grp = lane >> 2, tig = lane & 3;
#pragma unroll
    for (int nt = 0; nt < 16; nt++) {
        int col = nt*8 + 2*tig;
        float b0 = bias[col], b1 = bias[col+1];
        cc[nt][0] = b0; cc[nt][1] = b1;
        cc[nt][2] = b0; cc[nt][3] = b1;
    }
    const float* aWarp = sA + (w*16)*HS;
    const unsigned* Whi = g_whi[widx];
    const unsigned* Wlo = g_wlo[widx];

#pragma unroll
    for (int q = 0; q < 4; q++) {
        __syncthreads();   // previous consumers of sW done
        // stage quarter q: pure copy (uint4 = 4 consecutive k of one n)
        for (int o = t; o < 1024; o += 256) {
            int n = o >> 3, kb = o & 7;
            int gsrc = q*4096 + n*32 + kb*4;
            uint4 hv = *(const uint4*)(Whi + gsrc);
            uint4 lv = *(const uint4*)(Wlo + gsrc);
            *(uint4*)(sWhi + n*BS + kb*4) = hv;
            *(uint4*)(sWlo + n*BS + kb*4) = lv;
        }
        __syncthreads();

        const float* aq = aWarp + q*32;
#pragma unroll
        for (int kt = 0; kt < 4; kt++) {
            const float* ap = aq + grp*HS + kt*8 + tig;
            float r0 = ap[0];
            float r2 = ap[4];
            float r1 = ap[8*HS];
            float r3 = ap[8*HS + 4];
            unsigned a0h = tf32cvt(r0), a1h = tf32cvt(r1);
            unsigned a2h = tf32cvt(r2), a3h = tf32cvt(r3);
            unsigned a0l = tf32cvt(r0 - __uint_as_float(a0h));
            unsigned a1l = tf32cvt(r1 - __uint_as_float(a1h));
            unsigned a2l = tf32cvt(r2 - __uint_as_float(a2h));
            unsigned a3l = tf32cvt(r3 - __uint_as_float(a3h));
#pragma unroll
            for (int nt = 0; nt < 16; nt++) {
                const unsigned* bh = sWhi + (nt*8 + grp)*BS + kt*8 + tig;
                const unsigned* bl = sWlo + (nt*8 + grp)*BS + kt*8 + tig;
                unsigned b0h = bh[0], b1h = bh[4];
                unsigned b0l = bl[0], b1l = bl[4];
                MMA8(cc[nt], a0h,a1h,a2h,a3h, b0h,b1h);
                MMA8(cc[nt], a0l,a1l,a2l,a3l, b0h,b1h);
                MMA8(cc[nt], a0h,a1h,a2h,a3h, b0l,b1l);
            }
        }
    }
}

template<bool RELU>
__device__ __forceinline__ void tensor_store(float* __restrict__ dst, int S,
                                             float cc[16][4], int t) {
    const int lane = t & 31, w = t >> 5;
    const int grp = lane >> 2, tig = lane & 3;
    int row0 = w*16 + grp;
#pragma unroll
    for (int nt = 0; nt < 16; nt++) {
        int col = nt*8 + 2*tig;
        float2 v0 = make_float2(cc[nt][0], cc[nt][1]);
        float2 v1 = make_float2(cc[nt][2], cc[nt][3]);
        if (RELU) {
            v0.x = fmaxf(v0.x, 0.f); v0.y = fmaxf(v0.y, 0.f);
            v1.x = fmaxf(v1.x, 0.f); v1.y = fmaxf(v1.y, 0.f);
        }
        *(float2*)(dst + (size_t)row0 * S + col)     = v0;
        *(float2*)(dst + (size_t)(row0+8) * S + col) = v1;
    }
}
__device__ __forceinline__ void tensor_store_pos(float* __restrict__ sH,
                                                 float* __restrict__ posg,
                                                 float cc[16][4], int t) {
    const int lane = t & 31, w = t >> 5;
    const int grp = lane >> 2, tig = lane & 3;
    int row0 = w*16 + grp;
#pragma unroll
    for (int nt = 0; nt < 16; nt++) {
        int col = nt*8 + 2*tig;
        float2 v0 = make_float2(cc[nt][0], cc[nt][1]);
        float2 v1 = make_float2(cc[nt][2], cc[nt][3]);
        *(float2*)(sH + row0*HS + col)     = v0;
        *(float2*)(sH + (row0+8)*HS + col) = v1;
        *(float2*)(posg + (size_t)row0*128 + col)     = v0;
        *(float2*)(posg + (size_t)(row0+8)*128 + col) = v1;
    }
}

// ---------------------------------------------------------------------------
// Kernel 2: fused projections, tensor q/k/v. 128 rows/CTA, 256 thr, grid 128.
// ---------------------------------------------------------------------------
__global__ void __launch_bounds__(256, 2) proj_kernel(
    const float* __restrict__ feats,
    const float* __restrict__ fc1_w, const float* __restrict__ fc1_b)
{
    extern __shared__ float sm2[];
    unsigned* sWhi = (unsigned*)sm2;           // 4608
    unsigned* sWlo = (unsigned*)(sm2 + 4608);  // 4608
    float* sX = sm2 + 9216;                    // 16896 (128 x HS)
    int t = threadIdx.x;
    int g0 = blockIdx.x * 128;

    copyW(sX, feats + (size_t)g0*64, 2048, t);
    copyW((float*)sWhi, fc1_w, 2048, t);
    __syncthreads();

    ull acc[8][4];
    init_r8(acc, fc1_b, t);
    gemm_r8<64, 64>(acc, sX, (float*)sWhi, t);
    __syncthreads();                 // all reads of sX done
    store_r8<false>(sX, HS, acc, t); // x re-laid at stride HS

    float cc[16][4];
    tensor_gemm(cc, 3, g_zero, sX, sWhi, sWlo, t);
    tensor_store<false>(g_q + (size_t)g0*128, 128, cc, t);
    tensor_gemm(cc, 4, g_zero, sX, sWhi, sWlo, t);
    tensor_store<false>(g_k + (size_t)g0*128, 128, cc, t);
    tensor_gemm(cc, 5, g_zero, sX, sWhi, sWlo, t);
    tensor_store<false>(g_v + (size_t)g0*128, 128, cc, t);
}

// ---------------------------------------------------------------------------
// Kernel 3: fused main, tensor-core GEMMs (R15 structure, copy staging).
// 8 nodes (128 rows)/CTA, 256 threads, 2048 CTAs, 2 CTAs/SM.
// ---------------------------------------------------------------------------
__global__ void __launch_bounds__(256, 2) main_kernel(
    const float* __restrict__ xyz, const float* __restrict__ features,
    const float* __restrict__ d1_w, const float* __restrict__ d1_b,
    const float* __restrict__ d2_b, const float* __restrict__ g1_b,
    const float* __restrict__ g2_b,
    const float* __restrict__ fc2_w, const float* __restrict__ fc2_b,
    float* __restrict__ out)
{
    extern __shared__ float sm[];
    unsigned* sWhi = (unsigned*)sm;            // 4608
    unsigned* sWlo = (unsigned*)(sm + 4608);   // 4608
    float* sH   = sm + 9216;                   // 16896 (128 x 132)
    float* sRel = sm + 26112;                  // 384
    int*   sIdx = (int*)(sm + 26496);          // 128
    float* sRes = sm + 26624;                  // 1024 -> 27648 floats total

    int t = threadIdx.x;
    int g0 = blockIdx.x * 8;
    int bbase = g0 & ~(Nn - 1);
    float* posg = g_posbuf + (size_t)g0 * Kn * DM;

    // P0: idx + rel
    if (t < 128) {
        int j = g_idx[(size_t)g0*Kn + t];
        sIdx[t] = j;
        int nn = t >> 4;
        const float* pq = xyz + (size_t)(g0 + nn) * 3;
        const float* pj = xyz + (size_t)(bbase + j) * 3;
        sRel[t*3+0] = pq[0] - pj[0];
        sRel[t*3+1] = pq[1] - pj[1];
        sRel[t*3+2] = pq[2] - pj[2];
    }
    __syncthreads();

    // t1 = relu(rel@d1 + d1_b) -> sH (stride HS)
    for (int o4 = t; o4 < 4096; o4 += 256) {
        int r = o4 >> 5, c = (o4 & 31) * 4;
        float rx = sRel[r*3], ry = sRel[r*3+1], rz = sRel[r*3+2];
        float4 w0 = *(const float4*)(d1_w + c);
        float4 w1 = *(const float4*)(d1_w + 128 + c);
        float4 w2 = *(const float4*)(d1_w + 256 + c);
        float4 bb = *(const float4*)(d1_b + c);
        float4 v;
        v.x = fmaxf(fmaf(rz,w2.x,fmaf(ry,w1.x,fmaf(rx,w0.x,bb.x))), 0.f);
        v.y = fmaxf(fmaf(rz,w2.y,fmaf(ry,w1.y,fmaf(rx,w0.y,bb.y))), 0.f);
        v.z = fmaxf(fmaf(rz,w2.z,fmaf(ry,w1.z,fmaf(rx,w0.z,bb.z))), 0.f);
        v.w = fmaxf(fmaf(rz,w2.w,fmaf(ry,w1.w,fmaf(rx,w0.w,bb.w))), 0.f);
        *(float4*)(sH + r*HS + c) = v;
    }
    // (tensor_gemm starts with __syncthreads before staging)

    float cc[16][4];

    // pos = t1 @ d2 + d2_b
    tensor_gemm(cc, 0, d2_b, sH, sWhi, sWlo, t);
    tensor_store_pos(sH, posg, cc, t);     // own-stripe store
    __syncthreads();                        // h-phase reads all rows

    // h = q - k_gather + pos (in place)
    for (int o4 = t; o4 < 4096; o4 += 256) {
        int r = o4 >> 5, c = (o4 & 31) * 4;
        int nn = r >> 4;
        int j = sIdx[r];
        float4 kv = *(const float4*)(g_k + (size_t)(bbase + j)*128 + c);
        float4 qv = *(const float4*)(g_q + (size_t)(g0 + nn)*128 + c);
        float4 pv = *(const float4*)(sH + r*HS + c);
        float4 hh;
        hh.x = qv.x - kv.x + pv.x;
        hh.y = qv.y - kv.y + pv.y;
        hh.z = qv.z - kv.z + pv.z;
        hh.w = qv.w - kv.w + pv.w;
        *(float4*)(sH + r*HS + c) = hh;
    }
    __syncthreads();

    // a1 = relu(h @ g1 + g1_b)
    tensor_gemm(cc, 1, g1_b, sH, sWhi, sWlo, t);
    tensor_store<true>(sH, HS, cc, t);      // own-stripe: no sync needed

    // logits = a1 @ g2 + g2_b
    tensor_gemm(cc, 2, g2_b, sH, sWhi, sWlo, t);
    tensor_store<false>(sH, HS, cc, t);
    __syncthreads();                         // all mma done before sW reuse

    // stage fc2 (8192 floats) into sWhi..sWlo region (contiguous at sm)
    copyW(sm, fc2_w, 2048, t);
    __syncthreads();

    // softmax over K; attn in place; res -> sRes
    for (int p = t; p < 1024; p += 256) {
        int nn = p >> 7, c = p & 127;
        int r0n = nn << 4;
        float m = -3.4e38f;
#pragma unroll
        for (int k = 0; k < Kn; k++) m = fmaxf(m, sH[(r0n+k)*HS + c]);
        float e[Kn];
        float ssum = 0.f;
#pragma unroll
        for (int k = 0; k < Kn; k++) {
            e[k] = __expf((sH[(r0n+k)*HS + c] - m) * SCALE_F);
            ssum += e[k];
        }
        float inv = 1.f / ssum;
        float racc = 0.f;
#pragma unroll
        for (int k = 0; k < Kn; k++) {
            float a = e[k] * inv;
            sH[(r0n+k)*HS + c] = a;
            int j = sIdx[r0n + k];
            float vp = g_v[(size_t)(bbase + j)*128 + c] + posg[(size_t)(r0n+k)*128 + c];
            racc = fmaf(a, vp, racc);
        }
        sRes[nn*128 + c] = racc;
    }
    __syncthreads();

    // attn out
    {
        float* attn_base = out + (size_t)ATT_OFF + (size_t)g0 * (Kn * DM);
        for (int o4 = t; o4 < 4096; o4 += 256) {
            int r = o4 >> 5, c = (o4 & 31) * 4;
            *(float4*)(attn_base + r*128 + c) = *(const float4*)(sH + r*HS + c);
        }
    }

    // out = res @ fc2 + fc2_b + pre  (fc2 = sm[0..8192))
    for (int p = t; p < 512; p += 256) {
        int nn = p >> 6, d = p & 63;
        float a0 = fc2_b[d] + features[(size_t)(g0 + nn)*64 + d];
        const float* rr2 = sRes + nn*128;
#pragma unroll 8
        for (int c = 0; c < 128; c++)
            a0 = fmaf(rr2[c], sm[c*64 + d], a0);
        out[(size_t)(g0 + nn)*64 + d] = a0;
    }
}

// ---------------------------------------------------------------------------
extern "C" void kernel_launch(void* const* d_in, const int* in_sizes, int n_in,
                              void* d_out, int out_size) {
    const float* xyz   = (const float*)d_in[0];
    const float* feats = (const float*)d_in[1];
    const float* fc1_w = (const float*)d_in[2];
    const float* fc1_b = (const float*)d_in[3];
    const float* fc2_w = (const float*)d_in[4];
    const float* fc2_b = (const float*)d_in[5];
    const float* d1_w  = (const float*)d_in[6];
    const float* d1_b  = (const float*)d_in[7];
    const float* d2_w  = (const float*)d_in[8];
    const float* d2_b  = (const float*)d_in[9];
    const float* g1_w  = (const float*)d_in[10];
    const float* g1_b  = (const float*)d_in[11];
    const float* g2_w  = (const float*)d_in[12];
    const float* g2_b  = (const float*)d_in[13];
    const float* wq    = (const float*)d_in[14];
    const float* wk    = (const float*)d_in[15];
    const float* wv    = (const float*)d_in[16];
    float* outp = (float*)d_out;

    const int SMEM_KNN  = 65536;             // 64 KB
    const int SMEM_PROJ = 26112 * 4;         // 104448 B
    const int SMEM_MAIN = 27648 * 4;         // 110592 B
    cudaFuncSetAttribute(knn_kernel,  cudaFuncAttributeMaxDynamicSharedMemorySize, SMEM_KNN);
    cudaFuncSetAttribute(proj_kernel, cudaFuncAttributeMaxDynamicSharedMemorySize, SMEM_PROJ);
    cudaFuncSetAttribute(main_kernel, cudaFuncAttributeMaxDynamicSharedMemorySize, SMEM_MAIN);

    sort_kernel<<<Bn, 1024>>>(xyz);
    wsplit_kernel<<<384, 256>>>(d2_w, g1_w, g2_w, wq, wk, wv);
    knn_kernel<<<dim3(Nn/16, Bn), 512, SMEM_KNN>>>();
    proj_kernel<<<NODES/128, 256, SMEM_PROJ>>>(feats, fc1_w, fc1_b);
    main_kernel<<<NODES/8, 256, SMEM_MAIN>>>(xyz, feats,
                                             d1_w, d1_b, d2_b, g1_b, g2_b,
                                             fc2_w, fc2_b, outp);
}

// round 17
// speedup vs baseline: 1.2774x; 1.1641x over previous
#include <cuda_runtime.h>
#include <cuda_fp16.h>
#include <math.h>

// Problem constants
#define Bn 4
#define Nn 4096
#define Kn 16
#define DP 64
#define DM 128
#define NODES (Bn*Nn)            // 16384
#define ATT_OFF (NODES*DP)       // out region first, attn after
#define SCALE_F 0.08838834764831845f
#define FINF __int_as_float(0x7F800000)
#define KEY_INF 0xFFFFFFFFFFFFFFFFULL
#define HS 132                   // padded activation row stride (floats)

typedef unsigned long long ull;

// Scratch (device globals -- no allocation allowed)
__device__ int    g_idx[NODES*Kn];
__device__ float  g_q [NODES*DM];
__device__ float  g_k [NODES*DM];
__device__ float  g_v [NODES*DM];
__device__ float  g_posbuf[(size_t)NODES*Kn*DM];   // 128 MiB static scratch
__device__ float4 g_sp[NODES];                     // x-sorted (x,y,z,idx_bits)
__device__ float  g_zero[DM];                      // zero bias (static init)
// Pre-split fp16 hi/lo b-fragments: [w][q*1024 + n*8 + kc*4 + tig]
// uint4 = (b0h, b1h, b0l, b1l); b0 rows k0,k0+1; b1 rows k0+8,k0+9; col n.
// w: 0=d2 1=g1 2=g2 3=wq 4=wk 5=wv
__device__ uint4  g_wf16[6][4096];

// ---------------------------------------------------------------------------
// helpers
// ---------------------------------------------------------------------------
__device__ __forceinline__ ull pk2(float lo, float hi) {
    ull r;
    asm("mov.b64 %0, {%1,%2};" : "=l"(r)
        : "r"(__float_as_uint(lo)), "r"(__float_as_uint(hi)));
    return r;
}
__device__ __forceinline__ ull dup2f(float v) {
    ull r; unsigned u = __float_as_uint(v);
    asm("mov.b64 %0, {%1,%1};" : "=l"(r) : "r"(u));
    return r;
}
__device__ __forceinline__ void fma2(ull& d, ull a, ull b) {
    asm("fma.rn.f32x2 %0, %1, %2, %0;" : "+l"(d) : "l"(a), "l"(b));
}
__device__ __forceinline__ float2 up2(ull v) {
    unsigned lo, hi;
    asm("mov.b64 {%0,%1}, %2;" : "=r"(lo), "=r"(hi) : "l"(v));
    return make_float2(__uint_as_float(lo), __uint_as_float(hi));
}
// split a float2 into fp16 hi + fp16 lo (packed half2 bit patterns)
__device__ __forceinline__ void split16(float2 f, unsigned& uh, unsigned& ul) {
    __half2 h = __float22half2_rn(f);
    float2 r = __half22float2(h);
    __half2 l = __float22half2_rn(make_float2(f.x - r.x, f.y - r.y));
    uh = *(unsigned*)&h;
    ul = *(unsigned*)&l;
}
#define MMA16(c, a0,a1,a2,a3, b0,b1) \
    asm volatile("mma.sync.aligned.m16n8k16.row.col.f32.f16.f16.f32 " \
        "{%0,%1,%2,%3}, {%4,%5,%6,%7}, {%8,%9}, {%0,%1,%2,%3};" \
        : "+f"(c[0]), "+f"(c[1]), "+f"(c[2]), "+f"(c[3]) \
        : "r"(a0), "r"(a1), "r"(a2), "r"(a3), "r"(b0), "r"(b1))

// ---------------------------------------------------------------------------
// Kernel 0a: per-batch bitonic sort of points by x. grid Bn x 1024 threads.
// ---------------------------------------------------------------------------
__global__ void __launch_bounds__(1024) sort_kernel(const float* __restrict__ xyz) {
    __shared__ float skey[Nn];
    __shared__ int   sval[Nn];
    int t = threadIdx.x;
    int b = blockIdx.x;
    const float* base = xyz + (size_t)b * Nn * 3;
    for (int i = t; i < Nn; i += 1024) { skey[i] = base[i*3]; sval[i] = i; }
    __syncthreads();
    for (int k = 2; k <= Nn; k <<= 1) {
        for (int j = k >> 1; j > 0; j >>= 1) {
            for (int e = t; e < Nn; e += 1024) {
                int p = e ^ j;
                if (p > e) {
                    bool up = ((e & k) == 0);
                    float a = skey[e], c = skey[p];
                    if ((a > c) == up) {
                        skey[e] = c; skey[p] = a;
                        int tv = sval[e]; sval[e] = sval[p]; sval[p] = tv;
                    }
                }
            }
            __syncthreads();
        }
    }
    for (int i = t; i < Nn; i += 1024) {
        int id = sval[i];
        g_sp[b*Nn + i] = make_float4(skey[i], base[id*3 + 1], base[id*3 + 2],
                                     __int_as_float(id));
    }
}

// ---------------------------------------------------------------------------
// Kernel 0b: pre-split six 128x128 weights into fp16 hi/lo b-fragments.
// grid 96 x 256, one uint4 per thread.
// ---------------------------------------------------------------------------
__global__ void __launch_bounds__(256) wsplit_kernel(
    const float* __restrict__ d2, const float* __restrict__ g1,
    const float* __restrict__ g2, const float* __restrict__ wq,
    const float* __restrict__ wk, const float* __restrict__ wv)
{
    int gid = blockIdx.x * 256 + threadIdx.x;   // 0..24575
    int w   = gid >> 12;                        // 6 weights x 4096 frags
    int e   = gid & 4095;
    int q   = e >> 10;
    int r   = e & 1023;
    int n   = r >> 3;
    int c   = r & 7;
    int kc  = c >> 2, tig = c & 3;
    const float* W = (w == 0) ? d2 : (w == 1) ? g1 : (w == 2) ? g2
                   : (w == 3) ? wq : (w == 4) ? wk : wv;
    int k0 = q*32 + kc*16 + 2*tig;
    float2 f0 = make_float2(W[(size_t)k0*128 + n],     W[(size_t)(k0+1)*128 + n]);
    float2 f1 = make_float2(W[(size_t)(k0+8)*128 + n], W[(size_t)(k0+9)*128 + n]);
    unsigned b0h, b0l, b1h, b1l;
    split16(f0, b0h, b0l);
    split16(f1, b1h, b1l);
    g_wf16[w][e] = make_uint4(b0h, b1h, b0l, b1l);
}

// ---------------------------------------------------------------------------
// Kernel 1: warp-per-query windowed KNN on x-sorted points (R9, proven).
// ---------------------------------------------------------------------------
__global__ void __launch_bounds__(512) knn_kernel() {
    extern __shared__ float4 spts[];       // 4096 * 16B = 65536
    int t = threadIdx.x;
    int b = blockIdx.y;
    for (int i = t; i < Nn; i += 512) spts[i] = g_sp[b*Nn + i];
    __syncthreads();

    const unsigned full = 0xffffffffu;
    int lane = t & 31;
    int r = blockIdx.x * 16 + (t >> 5);

    float4 me = spts[r];
    float qx = me.x, qy = me.y, qz = me.z;
    int qid = __float_as_int(me.w);

    ull key = KEY_INF;
    if (lane == 0) key = (unsigned)qid;
    ull wk = __shfl_sync(full, key, 15);

    bool isL = lane < 16;
    int lo = r - 1, hi = r + 1;
    bool aliveL = true, aliveR = true;

    while (aliveL || aliveR) {
        ull  ckey = KEY_INF;
        float dxx = FINF;
        bool inr = false;
        int cand = isL ? (lo - lane) : (hi + (lane - 16));
        if (isL) inr = aliveL && (cand >= 0);
        else     inr = aliveR && (cand < Nn);
        if (inr) {
            float4 p = spts[cand];
            float dx = qx - p.x, dy = qy - p.y, dz = qz - p.z;
            dxx = __fmul_rn(dx, dx);
            float d = __fadd_rn(__fadd_rn(dxx, __fmul_rn(dy,dy)),
                                __fmul_rn(dz,dz));
            ckey = ((ull)__float_as_uint(d) << 32) |
                   (unsigned)__float_as_int(p.w);
        }

        unsigned ball = __ballot_sync(full, inr && ckey < wk);
        while (ball) {
            int s = __ffs(ball) - 1; ball &= ball - 1;
            ull k = __shfl_sync(full, ckey, s);
            if (k >= wk) continue;
            unsigned bl = __ballot_sync(full, isL && key < k);
            int pos = __popc(bl);
            ull up = __shfl_up_sync(full, key, 1);
            if (isL) {
                if (lane == pos) key = k;
                else if (lane > pos) key = up;
            }
            wk = __shfl_sync(full, key, 15);
        }

        float worstd = __uint_as_float((unsigned)(wk >> 32));
        float dxx15 = __shfl_sync(full, dxx, 15);
        float dxx31 = __shfl_sync(full, dxx, 31);
        int   inr15 = __shfl_sync(full, (int)inr, 15);
        int   inr31 = __shfl_sync(full, (int)inr, 31);
        aliveL = aliveL && inr15 && !(dxx15 > worstd);
        aliveR = aliveR && inr31 && !(dxx31 > worstd);
        lo -= 16; hi += 16;
    }

    if (isL)
        g_idx[((size_t)b*Nn + qid) * Kn + lane] =
            (int)(unsigned)(key & 0xffffffffu);
}

// ---------------------------------------------------------------------------
// Scalar f32x2 GEMM helpers (fc1 in proj)
// ---------------------------------------------------------------------------
template<int KD, int AS>
__device__ __forceinline__ void gemm_r8(ull acc[8][4],
                                        const float* __restrict__ sA,
                                        const float* __restrict__ sW, int t) {
    const int c0 = (t & 15) * 8;
    const int r0 = (t >> 4) * 8;
#pragma unroll 2
    for (int kk = 0; kk < KD; kk += 4) {
        float4 a4[8];
#pragma unroll
        for (int i = 0; i < 8; i++)
            a4[i] = *(const float4*)(sA + (r0 + i) * AS + kk);
#pragma unroll
        for (int kq = 0; kq < 4; kq++) {
            const float* wr = sW + (kk + kq) * 128 + c0;
            ulonglong2 wl = *(const ulonglong2*)(wr);
            ulonglong2 wh = *(const ulonglong2*)(wr + 4);
#pragma unroll
            for (int i = 0; i < 8; i++) {
                float av = (kq == 0) ? a4[i].x : (kq == 1) ? a4[i].y
                         : (kq == 2) ? a4[i].z : a4[i].w;
                ull ad = dup2f(av);
                fma2(acc[i][0], ad, wl.x);
                fma2(acc[i][1], ad, wl.y);
                fma2(acc[i][2], ad, wh.x);
                fma2(acc[i][3], ad, wh.y);
            }
        }
    }
}
__device__ __forceinline__ void init_r8(ull acc[8][4], const float* __restrict__ bias, int t) {
    const int c0 = (t & 15) * 8;
#pragma unroll
    for (int j = 0; j < 4; j++) {
        ull b2 = pk2(bias[c0 + 2*j], bias[c0 + 2*j + 1]);
#pragma unroll
        for (int i = 0; i < 8; i++) acc[i][j] = b2;
    }
}
template<bool RELU>
__device__ __forceinline__ void store_r8(float* __restrict__ dst, int stride,
                                         ull acc[8][4], int t) {
    const int c0 = (t & 15) * 8;
    const int r0 = (t >> 4) * 8;
#pragma unroll
    for (int i = 0; i < 8; i++) {
        float2 p0 = up2(acc[i][0]), p1 = up2(acc[i][1]);
        float2 p2 = up2(acc[i][2]), p3 = up2(acc[i][3]);
        float4 lo = make_float4(p0.x, p0.y, p1.x, p1.y);
        float4 hi = make_float4(p2.x, p2.y, p3.x, p3.y);
        if (RELU) {
            lo.x = fmaxf(lo.x, 0.f); lo.y = fmaxf(lo.y, 0.f);
            lo.z = fmaxf(lo.z, 0.f); lo.w = fmaxf(lo.w, 0.f);
            hi.x = fmaxf(hi.x, 0.f); hi.y = fmaxf(hi.y, 0.f);
            hi.z = fmaxf(hi.z, 0.f); hi.w = fmaxf(hi.w, 0.f);
        }
        *(float4*)(dst + (size_t)(r0 + i) * stride + c0)     = lo;
        *(float4*)(dst + (size_t)(r0 + i) * stride + c0 + 4) = hi;
    }
}
__device__ __forceinline__ void copyW(float* __restrict__ dst,
                                      const float* __restrict__ src, int n4, int t) {
    for (int o = t; o < n4; o += 256)
        *(float4*)(dst + o*4) = *(const float4*)(src + o*4);
}

// ---------------------------------------------------------------------------
// fp16 tensor GEMM (m16n8k16, 3-term hi/lo split). CTA 128x128; warp wid
// owns rows [16*wid, 16*wid+16). cc[16][4] fp32. A fp32 in sA (stride HS),
// split to fp16 on the fly. B staged per 32-k quarter from g_wf16:
// smem uint4 layout n*9 + kc*4 + tig (pad x9 => conflict-free everywhere).
// ---------------------------------------------------------------------------
__device__ __forceinline__ void tensor_gemm16(
    float cc[16][4], int widx,
    const float* __restrict__ bias,
    const float* __restrict__ sA,
    uint4* __restrict__ sWb, int t)
{
    const int lane = t & 31, wid = t >> 5;
    const int grp = lane >> 2, tig = lane & 3;
#pragma unroll
    for (int nt = 0; nt < 16; nt++) {
        int col = nt*8 + 2*tig;
        float b0 = bias[col], b1 = bias[col+1];
        cc[nt][0] = b0; cc[nt][1] = b1;
        cc[nt][2] = b0; cc[nt][3] = b1;
    }
    const float* aWarp = sA + (wid*16)*HS;
    const uint4* Wsrc = g_wf16[widx];

#pragma unroll
    for (int q = 0; q < 4; q++) {
        __syncthreads();   // previous consumers of sWb done
        for (int o = t; o < 1024; o += 256) {
            int n = o >> 3, c = o & 7;
            sWb[n*9 + c] = Wsrc[q*1024 + o];
        }
        __syncthreads();

#pragma unroll
        for (int kc = 0; kc < 2; kc++) {
            const float* ap = aWarp + grp*HS + q*32 + kc*16 + 2*tig;
            float2 f00 = *(const float2*)(ap);            // row grp,  k lo
            float2 f01 = *(const float2*)(ap + 8);        // row grp,  k hi
            float2 f10 = *(const float2*)(ap + 8*HS);     // row grp+8, k lo
            float2 f11 = *(const float2*)(ap + 8*HS + 8); // row grp+8, k hi
            unsigned ah0, al0, ah1, al1, ah2, al2, ah3, al3;
            split16(f00, ah0, al0);
            split16(f10, ah1, al1);
            split16(f01, ah2, al2);
            split16(f11, ah3, al3);
#pragma unroll
            for (int nt = 0; nt < 16; nt++) {
                uint4 bb = sWb[(nt*8 + grp)*9 + kc*4 + tig];
                MMA16(cc[nt], ah0,ah1,ah2,ah3, bb.x, bb.y);
                MMA16(cc[nt], al0,al1,al2,al3, bb.x, bb.y);
                MMA16(cc[nt], ah0,ah1,ah2,ah3, bb.z, bb.w);
            }
        }
    }
}

template<bool RELU>
__device__ __forceinline__ void tensor_store(float* __restrict__ dst, int S,
                                             float cc[16][4], int t) {
    const int lane = t & 31, wid = t >> 5;
    const int grp = lane >> 2, tig = lane & 3;
    int row0 = wid*16 + grp;
#pragma unroll
    for (int nt = 0; nt < 16; nt++) {
        int col = nt*8 + 2*tig;
        float2 v0 = make_float2(cc[nt][0], cc[nt][1]);
        float2 v1 = make_float2(cc[nt][2], cc[nt][3]);
        if (RELU) {
            v0.x = fmaxf(v0.x, 0.f); v0.y = fmaxf(v0.y, 0.f);
            v1.x = fmaxf(v1.x, 0.f); v1.y = fmaxf(v1.y, 0.f);
        }
        *(float2*)(dst + (size_t)row0 * S + col)     = v0;
        *(float2*)(dst + (size_t)(row0+8) * S + col) = v1;
    }
}
__device__ __forceinline__ void tensor_store_pos(float* __restrict__ sH,
                                                 float* __restrict__ posg,
                                                 float cc[16][4], int t) {
    const int lane = t & 31, wid = t >> 5;
    const int grp = lane >> 2, tig = lane & 3;
    int row0 = wid*16 + grp;
#pragma unroll
    for (int nt = 0; nt < 16; nt++) {
        int col = nt*8 + 2*tig;
        float2 v0 = make_float2(cc[nt][0], cc[nt][1]);
        float2 v1 = make_float2(cc[nt][2], cc[nt][3]);
        *(float2*)(sH + row0*HS + col)     = v0;
        *(float2*)(sH + (row0+8)*HS + col) = v1;
        *(float2*)(posg + (size_t)row0*128 + col)     = v0;
        *(float2*)(posg + (size_t)(row0+8)*128 + col) = v1;
    }
}

// ---------------------------------------------------------------------------
// Kernel 2: projections. grid (128, 3): y selects q/k/v. 256 threads.
// Each CTA: fc1 (scalar, recomputed) then ONE tensor gemm.
// smem: sWb 1152 uint4 (4608 floats) + sX 16896 = 21504 floats (86016 B).
// ---------------------------------------------------------------------------
__global__ void __launch_bounds__(256, 2) proj_kernel(
    const float* __restrict__ feats,
    const float* __restrict__ fc1_w, const float* __restrict__ fc1_b)
{
    extern __shared__ float sm2[];
    uint4* sWb = (uint4*)sm2;                  // 1152 uint4
    float* sX  = sm2 + 4608;                   // 16896 (128 x HS)
    int t = threadIdx.x;
    int g0 = blockIdx.x * 128;
    int by = blockIdx.y;

    copyW(sX, feats + (size_t)g0*64, 2048, t);          // feats, stride 64
    copyW(sX + 8448, fc1_w, 2048, t);                   // fc1_w after feats
    __syncthreads();

    ull acc[8][4];
    init_r8(acc, fc1_b, t);
    gemm_r8<64, 64>(acc, sX, sX + 8448, t);
    __syncthreads();                 // all reads of sX done
    store_r8<false>(sX, HS, acc, t); // x re-laid at stride HS

    float cc[16][4];
    tensor_gemm16(cc, 3 + by, g_zero, sX, sWb, t);
    float* outp = (by == 0) ? g_q : (by == 1) ? g_k : g_v;
    tensor_store<false>(outp + (size_t)g0*128, 128, cc, t);
}

// ---------------------------------------------------------------------------
// Kernel 3: fused main, fp16 tensor GEMMs. 8 nodes (128 rows)/CTA, 256 thr,
// 2048 CTAs, 2 CTAs/SM. smem 92160 B.
// ---------------------------------------------------------------------------
__global__ void __launch_bounds__(256, 2) main_kernel(
    const float* __restrict__ xyz, const float* __restrict__ features,
    const float* __restrict__ d1_w, const float* __restrict__ d1_b,
    const float* __restrict__ d2_b, const float* __restrict__ g1_b,
    const float* __restrict__ g2_b,
    const float* __restrict__ fc2_w, const float* __restrict__ fc2_b,
    float* __restrict__ out)
{
    extern __shared__ float sm[];
    uint4* sWb  = (uint4*)sm;                  // 1152 uint4 = 4608 floats
    float* sH   = sm + 4608;                   // 16896 (128 x 132)
    float* sRel = sm + 21504;                  // 384
    int*   sIdx = (int*)(sm + 21888);          // 128
    float* sRes = sm + 22016;                  // 1024 -> 23040 floats total

    int t = threadIdx.x;
    int g0 = blockIdx.x * 8;
    int bbase = g0 & ~(Nn - 1);
    float* posg = g_posbuf + (size_t)g0 * Kn * DM;

    // P0: idx + rel
    if (t < 128) {
        int j = g_idx[(size_t)g0*Kn + t];
        sIdx[t] = j;
        int nn = t >> 4;
        const float* pq = xyz + (size_t)(g0 + nn) * 3;
        const float* pj = xyz + (size_t)(bbase + j) * 3;
        sRel[t*3+0] = pq[0] - pj[0];
        sRel[t*3+1] = pq[1] - pj[1];
        sRel[t*3+2] = pq[2] - pj[2];
    }
    __syncthreads();

    // t1 = relu(rel@d1 + d1_b) -> sH (stride HS)
    for (int o4 = t; o4 < 4096; o4 += 256) {
        int r = o4 >> 5, c = (o4 & 31) * 4;
        float rx = sRel[r*3], ry = sRel[r*3+1], rz = sRel[r*3+2];
        float4 w0 = *(const float4*)(d1_w + c);
        float4 w1 = *(const float4*)(d1_w + 128 + c);
        float4 w2 = *(const float4*)(d1_w + 256 + c);
        float4 bb = *(const float4*)(d1_b + c);
        float4 v;
        v.x = fmaxf(fmaf(rz,w2.x,fmaf(ry,w1.x,fmaf(rx,w0.x,bb.x))), 0.f);
        v.y = fmaxf(fmaf(rz,w2.y,fmaf(ry,w1.y,fmaf(rx,w0.y,bb.y))), 0.f);
        v.z = fmaxf(fmaf(rz,w2.z,fmaf(ry,w1.z,fmaf(rx,w0.z,bb.z))), 0.f);
        v.w = fmaxf(fmaf(rz,w2.w,fmaf(ry,w1.w,fmaf(rx,w0.w,bb.w))), 0.f);
        *(float4*)(sH + r*HS + c) = v;
    }
    // (tensor_gemm16 starts with __syncthreads before staging)

    float cc[16][4];

    // pos = t1 @ d2 + d2_b
    tensor_gemm16(cc, 0, d2_b, sH, sWb, t);
    tensor_store_pos(sH, posg, cc, t);     // own-stripe store
    __syncthreads();                        // h-phase reads all rows

    // h = q - k_gather + pos (in place)
    for (int o4 = t; o4 < 4096; o4 += 256) {
        int r = o4 >> 5, c = (o4 & 31) * 4;
        int nn = r >> 4;
        int j = sIdx[r];
        float4 kv = *(const float4*)(g_k + (size_t)(bbase + j)*128 + c);
        float4 qv = *(const float4*)(g_q + (size_t)(g0 + nn)*128 + c);
        float4 pv = *(const float4*)(sH + r*HS + c);
        float4 hh;
        hh.x = qv.x - kv.x + pv.x;
        hh.y = qv.y - kv.y + pv.y;
        hh.z = qv.z - kv.z + pv.z;
        hh.w = qv.w - kv.w + pv.w;
        *(float4*)(sH + r*HS + c) = hh;
    }
    __syncthreads();

    // a1 = relu(h @ g1 + g1_b)
    tensor_gemm16(cc, 1, g1_b, sH, sWb, t);
    tensor_store<true>(sH, HS, cc, t);      // own-stripe: no sync needed

    // logits = a1 @ g2 + g2_b
    tensor_gemm16(cc, 2, g2_b, sH, sWb, t);
    tensor_store<false>(sH, HS, cc, t);
    __syncthreads();

    // softmax over K; attn in place; res -> sRes
    for (int p = t; p < 1024; p += 256) {
        int nn = p >> 7, c = p & 127;
        int r0n = nn << 4;
        float m = -3.4e38f;
#pragma unroll
        for (int k = 0; k < Kn; k++) m = fmaxf(m, sH[(r0n+k)*HS + c]);
        float e[Kn];
        float ssum = 0.f;
#pragma unroll
        for (int k = 0; k < Kn; k++) {
            e[k] = __expf((sH[(r0n+k)*HS + c] - m) * SCALE_F);
            ssum += e[k];
        }
        float inv = 1.f / ssum;
        float racc = 0.f;
#pragma unroll
        for (int k = 0; k < Kn; k++) {
            float a = e[k] * inv;
            sH[(r0n+k)*HS + c] = a;
            int j = sIdx[r0n + k];
            float vp = g_v[(size_t)(bbase + j)*128 + c] + posg[(size_t)(r0n+k)*128 + c];
            racc = fmaf(a, vp, racc);
        }
        sRes[nn*128 + c] = racc;
    }
    __syncthreads();

    // attn out
    {
        float* attn_base = out + (size_t)ATT_OFF + (size_t)g0 * (Kn * DM);
        for (int o4 = t; o4 < 4096; o4 += 256) {
            int r = o4 >> 5, c = (o4 & 31) * 4;
            *(float4*)(attn_base + r*128 + c) = *(const float4*)(sH + r*HS + c);
        }
    }
    __syncthreads();    // attn fully written before sH is reused for fc2

    // fc2 -> sH (free now), then epilogue
    copyW(sH, fc2_w, 2048, t);
    __syncthreads();

    // out = res @ fc2 + fc2_b + pre
    for (int p = t; p < 512; p += 256) {
        int nn = p >> 6, d = p & 63;
        float a0 = fc2_b[d] + features[(size_t)(g0 + nn)*64 + d];
        const float* rr2 = sRes + nn*128;
#pragma unroll 8
        for (int c = 0; c < 128; c++)
            a0 = fmaf(rr2[c], sH[c*64 + d], a0);
        out[(size_t)(g0 + nn)*64 + d] = a0;
    }
}

// ---------------------------------------------------------------------------
extern "C" void kernel_launch(void* const* d_in, const int* in_sizes, int n_in,
                              void* d_out, int out_size) {
    const float* xyz   = (const float*)d_in[0];
    const float* feats = (const float*)d_in[1];
    const float* fc1_w = (const float*)d_in[2];
    const float* fc1_b = (const float*)d_in[3];
    const float* fc2_w = (const float*)d_in[4];
    const float* fc2_b = (const float*)d_in[5];
    const float* d1_w  = (const float*)d_in[6];
    const float* d1_b  = (const float*)d_in[7];
    const float* d2_w  = (const float*)d_in[8];
    const float* d2_b  = (const float*)d_in[9];
    const float* g1_w  = (const float*)d_in[10];
    const float* g1_b  = (const float*)d_in[11];
    const float* g2_w  = (const float*)d_in[12];
    const float* g2_b  = (const float*)d_in[13];
    const float* wq    = (const float*)d_in[14];
    const float* wk    = (const float*)d_in[15];
    const float* wv    = (const float*)d_in[16];
    float* outp = (float*)d_out;

    const int SMEM_KNN  = 65536;             // 64 KB
    const int SMEM_PROJ = 21504 * 4;         // 86016 B
    const int SMEM_MAIN = 23040 * 4;         // 92160 B
    cudaFuncSetAttribute(knn_kernel,  cudaFuncAttributeMaxDynamicSharedMemorySize, SMEM_KNN);
    cudaFuncSetAttribute(proj_kernel, cudaFuncAttributeMaxDynamicSharedMemorySize, SMEM_PROJ);
    cudaFuncSetAttribute(main_kernel, cudaFuncAttributeMaxDynamicSharedMemorySize, SMEM_MAIN);

    sort_kernel<<<Bn, 1024>>>(xyz);
    wsplit_kernel<<<96, 256>>>(d2_w, g1_w, g2_w, wq, wk, wv);
    knn_kernel<<<dim3(Nn/16, Bn), 512, SMEM_KNN>>>();
    proj_kernel<<<dim3(NODES/128, 3), 256, SMEM_PROJ>>>(feats, fc1_w, fc1_b);
    main_kernel<<<NODES/8, 256, SMEM_MAIN>>>(xyz, feats,
                                             d1_w, d1_b, d2_b, g1_b, g2_b,
                                             fc2_w, fc2_b, outp);
}